// round 1
// baseline (speedup 1.0000x reference)
#include <cuda_runtime.h>
#include <math.h>

#define NBINS 229
#define OUTF  88
#define MODEL 128
#define WSZ   30
#define WIN   61
#define TSEQ  1024
#define NTOK  4096   // B*T = 4*1024

// Output layout (floats), tuple order: frame_pred, a_frame, onset_pred, a_onset, feat_pred
#define FRAME_OFF  0
#define AFRAME_OFF (NTOK*OUTF)                    // 360448
#define ONSET_OFF  (AFRAME_OFF + NTOK*WIN)        // 610304
#define AONSET_OFF (ONSET_OFF + NTOK*OUTF)        // 970752
#define FEAT_OFF   (AONSET_OFF + NTOK*WIN)        // 1220608

// Scratch (allocation-free rule: __device__ globals)
__device__ float g_go[NTOK*MODEL];   // g_onset[t] = spec[t] @ Wao[0:229] + b_attn_o
__device__ float g_uo[NTOK*MODEL];   // u_onset[t'] = spec[t'] @ Wao[229:458]
__device__ float g_uc[NTOK*MODEL];   // u_comb[t']  = spec[t'] @ Wac[176:405]

// ---------------------------------------------------------------------------
// Kernel 1: fused projection GEMM  [NTOK x 229] @ [229 x 472]
//   cols   0.. 87 : feat_pred  (+b_frame)  -> d_out FEAT region
//   cols  88..215 : g_o        (+b_attn_o) -> g_go
//   cols 216..343 : u_o                     -> g_uo
//   cols 344..471 : u_c                     -> g_uc
// ---------------------------------------------------------------------------
#define K1_TT 16
__global__ void __launch_bounds__(512) k1_proj(
    const float* __restrict__ spec,
    const float* __restrict__ Wf,  const float* __restrict__ bf,
    const float* __restrict__ Wao, const float* __restrict__ bao,
    const float* __restrict__ Wac,
    float* __restrict__ out)
{
    __shared__ float sh[NBINS][20];   // [k][tt], padded to 20 for banks, 16B-aligned rows
    const int tok0 = blockIdx.x * K1_TT;

    for (int idx = threadIdx.x; idx < NBINS * K1_TT; idx += blockDim.x) {
        int tt = idx / NBINS;
        int k  = idx - tt * NBINS;
        sh[k][tt] = spec[(size_t)(tok0 + tt) * NBINS + k];
    }
    __syncthreads();

    const int j = threadIdx.x;
    if (j >= 472) return;

    const float* wp;
    int stride;
    float bias = 0.f;
    if (j < 88)       { wp = Wf + j;                    stride = OUTF;  bias = bf[j]; }
    else if (j < 216) { wp = Wao + (j - 88);            stride = MODEL; bias = bao[j - 88]; }
    else if (j < 344) { wp = Wao + NBINS*MODEL + (j - 216); stride = MODEL; }
    else              { wp = Wac + 176*MODEL  + (j - 344);  stride = MODEL; }

    float acc[K1_TT];
    #pragma unroll
    for (int i = 0; i < K1_TT; i++) acc[i] = 0.f;

    #pragma unroll 4
    for (int k = 0; k < NBINS; k++) {
        float w = *wp; wp += stride;
        const float4* row = reinterpret_cast<const float4*>(&sh[k][0]);
        float4 s0 = row[0], s1 = row[1], s2 = row[2], s3 = row[3];
        acc[0]  += s0.x * w; acc[1]  += s0.y * w; acc[2]  += s0.z * w; acc[3]  += s0.w * w;
        acc[4]  += s1.x * w; acc[5]  += s1.y * w; acc[6]  += s1.z * w; acc[7]  += s1.w * w;
        acc[8]  += s2.x * w; acc[9]  += s2.y * w; acc[10] += s2.z * w; acc[11] += s2.w * w;
        acc[12] += s3.x * w; acc[13] += s3.y * w; acc[14] += s3.z * w; acc[15] += s3.w * w;
    }

    if (j < 88) {
        #pragma unroll
        for (int tt = 0; tt < K1_TT; tt++)
            out[FEAT_OFF + (size_t)(tok0 + tt) * OUTF + j] = acc[tt] + bias;
    } else if (j < 216) {
        int m = j - 88;
        #pragma unroll
        for (int tt = 0; tt < K1_TT; tt++)
            g_go[(size_t)(tok0 + tt) * MODEL + m] = acc[tt] + bias;
    } else if (j < 344) {
        int m = j - 216;
        #pragma unroll
        for (int tt = 0; tt < K1_TT; tt++)
            g_uo[(size_t)(tok0 + tt) * MODEL + m] = acc[tt];
    } else {
        int m = j - 344;
        #pragma unroll
        for (int tt = 0; tt < K1_TT; tt++)
            g_uc[(size_t)(tok0 + tt) * MODEL + m] = acc[tt];
    }
}

// ---------------------------------------------------------------------------
// Kernel 2: per-token attention + epilogues. One block per token, 256 threads.
// ---------------------------------------------------------------------------
__device__ __forceinline__ float warp_sum(float v) {
    v += __shfl_xor_sync(0xFFFFFFFFu, v, 16);
    v += __shfl_xor_sync(0xFFFFFFFFu, v, 8);
    v += __shfl_xor_sync(0xFFFFFFFFu, v, 4);
    v += __shfl_xor_sync(0xFFFFFFFFu, v, 2);
    v += __shfl_xor_sync(0xFFFFFFFFu, v, 1);
    return v;
}
__device__ __forceinline__ float warp_max(float v) {
    v = fmaxf(v, __shfl_xor_sync(0xFFFFFFFFu, v, 16));
    v = fmaxf(v, __shfl_xor_sync(0xFFFFFFFFu, v, 8));
    v = fmaxf(v, __shfl_xor_sync(0xFFFFFFFFu, v, 4));
    v = fmaxf(v, __shfl_xor_sync(0xFFFFFFFFu, v, 2));
    v = fmaxf(v, __shfl_xor_sync(0xFFFFFFFFu, v, 1));
    return v;
}

__global__ void __launch_bounds__(256) k2_attn(
    const float* __restrict__ spec,
    const float* __restrict__ vo,  const float* __restrict__ vc,
    const float* __restrict__ Wl1, const float* __restrict__ bl1,
    const float* __restrict__ Wac, const float* __restrict__ bac,
    const float* __restrict__ Wlc, const float* __restrict__ blc,
    float* __restrict__ out)
{
    const int tok = blockIdx.x;
    const int b   = tok >> 10;
    const int t   = tok & (TSEQ - 1);
    const int tid = threadIdx.x;
    const int warp = tid >> 5;
    const int lane = tid & 31;

    __shared__ float g[MODEL];
    __shared__ float vv[MODEL];
    __shared__ float sc[64];
    __shared__ float aw[64];
    __shared__ float wsum[NBINS];
    __shared__ float x[2 * OUTF];     // [feat(88), onset(88)]
    __shared__ float gc[MODEL];

    // Load g_o, v_o; load feat_pred (written by k1) into x[0:88]
    if (tid < MODEL) {
        g[tid]  = g_go[(size_t)tok * MODEL + tid];
        vv[tid] = vo[tid];
    }
    if (tid >= 128 && tid < 128 + OUTF) {
        x[tid - 128] = out[FEAT_OFF + (size_t)tok * OUTF + (tid - 128)];
    }
    __syncthreads();

    // ---- Onset attention scores ----
    for (int w = warp; w < WIN; w += 8) {
        int tp = t + w - WSZ;
        bool valid = (tp >= 0) && (tp < TSEQ);
        const float* up = g_uo + (size_t)(b * TSEQ + tp) * MODEL;
        float p = 0.f;
        #pragma unroll
        for (int mi = 0; mi < 4; mi++) {
            int m = lane + mi * 32;
            float u = valid ? up[m] : 0.f;
            p += vv[m] * tanhf(g[m] + u);
        }
        p = warp_sum(p);
        if (lane == 0) sc[w] = p;
    }
    __syncthreads();

    // ---- Softmax (warp 0), write a_onset ----
    if (warp == 0) {
        float s0 = (lane < WIN) ? sc[lane] : -1e30f;
        float s1 = (lane + 32 < WIN) ? sc[lane + 32] : -1e30f;
        float mx = warp_max(fmaxf(s0, s1));
        float e0 = (lane < WIN) ? expf(s0 - mx) : 0.f;
        float e1 = (lane + 32 < WIN) ? expf(s1 - mx) : 0.f;
        float ssum = warp_sum(e0 + e1);
        float inv = 1.f / ssum;
        if (lane < WIN) {
            float a = e0 * inv;
            aw[lane] = a;
            out[AONSET_OFF + (size_t)tok * WIN + lane] = a;
        }
        if (lane + 32 < WIN) {
            float a = e1 * inv;
            aw[lane + 32] = a;
            out[AONSET_OFF + (size_t)tok * WIN + lane + 32] = a;
        }
    }
    __syncthreads();

    // ---- weighted_o = sum_w a[w] * spec[t+w-30, f] ----
    if (tid < NBINS) {
        float acc = 0.f;
        #pragma unroll 4
        for (int w = 0; w < WIN; w++) {
            int tp = t + w - WSZ;
            if (tp >= 0 && tp < TSEQ)
                acc += aw[w] * spec[(size_t)(b * TSEQ + tp) * NBINS + tid];
        }
        wsum[tid] = acc;
    }
    __syncthreads();

    // ---- onset_pred = sigmoid(weighted_o @ Wl1 + bl1) ----
    if (tid < OUTF) {
        float s = bl1[tid];
        #pragma unroll 4
        for (int k = 0; k < NBINS; k++)
            s += wsum[k] * Wl1[k * OUTF + tid];
        float o = 1.f / (1.f + expf(-s));
        out[ONSET_OFF + (size_t)tok * OUTF + tid] = o;
        x[OUTF + tid] = o;
    }
    __syncthreads();

    // ---- g_c = x @ Wac[0:176] + bac ; also swap in v_c ----
    if (tid < MODEL) {
        float s = bac[tid];
        #pragma unroll 4
        for (int k = 0; k < 2 * OUTF; k++)
            s += x[k] * Wac[k * MODEL + tid];
        gc[tid] = s;
        vv[tid] = vc[tid];
    }
    __syncthreads();

    // ---- Combine attention scores ----
    for (int w = warp; w < WIN; w += 8) {
        int tp = t + w - WSZ;
        bool valid = (tp >= 0) && (tp < TSEQ);
        const float* up = g_uc + (size_t)(b * TSEQ + tp) * MODEL;
        float p = 0.f;
        #pragma unroll
        for (int mi = 0; mi < 4; mi++) {
            int m = lane + mi * 32;
            float u = valid ? up[m] : 0.f;
            p += vv[m] * tanhf(gc[m] + u);
        }
        p = warp_sum(p);
        if (lane == 0) sc[w] = p;
    }
    __syncthreads();

    // ---- Softmax (warp 0), write a_frame ----
    if (warp == 0) {
        float s0 = (lane < WIN) ? sc[lane] : -1e30f;
        float s1 = (lane + 32 < WIN) ? sc[lane + 32] : -1e30f;
        float mx = warp_max(fmaxf(s0, s1));
        float e0 = (lane < WIN) ? expf(s0 - mx) : 0.f;
        float e1 = (lane + 32 < WIN) ? expf(s1 - mx) : 0.f;
        float ssum = warp_sum(e0 + e1);
        float inv = 1.f / ssum;
        if (lane < WIN) {
            float a = e0 * inv;
            aw[lane] = a;
            out[AFRAME_OFF + (size_t)tok * WIN + lane] = a;
        }
        if (lane + 32 < WIN) {
            float a = e1 * inv;
            aw[lane + 32] = a;
            out[AFRAME_OFF + (size_t)tok * WIN + lane + 32] = a;
        }
    }
    __syncthreads();

    // ---- weighted_c ----
    if (tid < NBINS) {
        float acc = 0.f;
        #pragma unroll 4
        for (int w = 0; w < WIN; w++) {
            int tp = t + w - WSZ;
            if (tp >= 0 && tp < TSEQ)
                acc += aw[w] * spec[(size_t)(b * TSEQ + tp) * NBINS + tid];
        }
        wsum[tid] = acc;
    }
    __syncthreads();

    // ---- frame_pred = sigmoid([x, weighted_c] @ Wlc + blc) ----
    if (tid < OUTF) {
        float s = blc[tid];
        #pragma unroll 4
        for (int k = 0; k < 2 * OUTF; k++)
            s += x[k] * Wlc[k * OUTF + tid];
        #pragma unroll 4
        for (int k = 0; k < NBINS; k++)
            s += wsum[k] * Wlc[(2 * OUTF + k) * OUTF + tid];
        out[FRAME_OFF + (size_t)tok * OUTF + tid] = 1.f / (1.f + expf(-s));
    }
}

extern "C" void kernel_launch(void* const* d_in, const int* in_sizes, int n_in,
                              void* d_out, int out_size)
{
    const float* spec = (const float*)d_in[0];
    const float* Wf   = (const float*)d_in[1];
    const float* bf   = (const float*)d_in[2];
    const float* Wao  = (const float*)d_in[3];
    const float* bao  = (const float*)d_in[4];
    const float* vo   = (const float*)d_in[5];
    const float* Wl1  = (const float*)d_in[6];
    const float* bl1  = (const float*)d_in[7];
    const float* Wac  = (const float*)d_in[8];
    const float* bac  = (const float*)d_in[9];
    const float* vc   = (const float*)d_in[10];
    const float* Wlc  = (const float*)d_in[11];
    const float* blc  = (const float*)d_in[12];
    float* out = (float*)d_out;

    k1_proj<<<NTOK / K1_TT, 512>>>(spec, Wf, bf, Wao, bao, Wac, out);
    k2_attn<<<NTOK, 256>>>(spec, vo, vc, Wl1, bl1, Wac, bac, Wlc, blc, out);
}

// round 2
// speedup vs baseline: 1.0605x; 1.0605x over previous
#include <cuda_runtime.h>
#include <math.h>

#define NBINS 229
#define OUTF  88
#define MODEL 128
#define WSZ   30
#define WIN   61
#define TSEQ  1024
#define NTOK  4096   // B*T = 4*1024

// Output layout (floats), tuple order: frame_pred, a_frame, onset_pred, a_onset, feat_pred
#define FRAME_OFF  0
#define AFRAME_OFF (NTOK*OUTF)
#define ONSET_OFF  (AFRAME_OFF + NTOK*WIN)
#define AONSET_OFF (ONSET_OFF + NTOK*OUTF)
#define FEAT_OFF   (AONSET_OFF + NTOK*WIN)

// Scratch (allocation-free rule: __device__ globals)
__device__ float g_go[NTOK*MODEL];
__device__ float g_uo[NTOK*MODEL];
__device__ float g_uc[NTOK*MODEL];

__device__ __forceinline__ float tanh_fast(float x) {
    float y;
    asm("tanh.approx.f32 %0, %1;" : "=f"(y) : "f"(x));
    return y;
}
__device__ __forceinline__ float sigmoid_fast(float x) {
    return 1.f / (1.f + __expf(-x));
}

// ---------------------------------------------------------------------------
// Kernel 1: fused projection GEMM  [NTOK x 229] @ [229 x 472]
// ---------------------------------------------------------------------------
#define K1_TT 16
__global__ void __launch_bounds__(512) k1_proj(
    const float* __restrict__ spec,
    const float* __restrict__ Wf,  const float* __restrict__ bf,
    const float* __restrict__ Wao, const float* __restrict__ bao,
    const float* __restrict__ Wac,
    float* __restrict__ out)
{
    __shared__ float sh[NBINS][20];
    const int tok0 = blockIdx.x * K1_TT;

    for (int idx = threadIdx.x; idx < NBINS * K1_TT; idx += blockDim.x) {
        int tt = idx / NBINS;
        int k  = idx - tt * NBINS;
        sh[k][tt] = spec[(size_t)(tok0 + tt) * NBINS + k];
    }
    __syncthreads();

    const int j = threadIdx.x;
    if (j >= 472) return;

    const float* wp;
    int stride;
    float bias = 0.f;
    if (j < 88)       { wp = Wf + j;                        stride = OUTF;  bias = bf[j]; }
    else if (j < 216) { wp = Wao + (j - 88);                stride = MODEL; bias = bao[j - 88]; }
    else if (j < 344) { wp = Wao + NBINS*MODEL + (j - 216); stride = MODEL; }
    else              { wp = Wac + 176*MODEL  + (j - 344);  stride = MODEL; }

    float acc[K1_TT];
    #pragma unroll
    for (int i = 0; i < K1_TT; i++) acc[i] = 0.f;

    #pragma unroll 4
    for (int k = 0; k < NBINS; k++) {
        float w = *wp; wp += stride;
        const float4* row = reinterpret_cast<const float4*>(&sh[k][0]);
        float4 s0 = row[0], s1 = row[1], s2 = row[2], s3 = row[3];
        acc[0]  += s0.x * w; acc[1]  += s0.y * w; acc[2]  += s0.z * w; acc[3]  += s0.w * w;
        acc[4]  += s1.x * w; acc[5]  += s1.y * w; acc[6]  += s1.z * w; acc[7]  += s1.w * w;
        acc[8]  += s2.x * w; acc[9]  += s2.y * w; acc[10] += s2.z * w; acc[11] += s2.w * w;
        acc[12] += s3.x * w; acc[13] += s3.y * w; acc[14] += s3.z * w; acc[15] += s3.w * w;
    }

    if (j < 88) {
        #pragma unroll
        for (int tt = 0; tt < K1_TT; tt++)
            out[FEAT_OFF + (size_t)(tok0 + tt) * OUTF + j] = acc[tt] + bias;
    } else if (j < 216) {
        int m = j - 88;
        #pragma unroll
        for (int tt = 0; tt < K1_TT; tt++)
            g_go[(size_t)(tok0 + tt) * MODEL + m] = acc[tt] + bias;
    } else if (j < 344) {
        int m = j - 216;
        #pragma unroll
        for (int tt = 0; tt < K1_TT; tt++)
            g_uo[(size_t)(tok0 + tt) * MODEL + m] = acc[tt];
    } else {
        int m = j - 344;
        #pragma unroll
        for (int tt = 0; tt < K1_TT; tt++)
            g_uc[(size_t)(tok0 + tt) * MODEL + m] = acc[tt];
    }
}

// ---------------------------------------------------------------------------
// Kernel 2: per-token attention + epilogues. One block per token, 256 threads.
// ---------------------------------------------------------------------------
__device__ __forceinline__ float warp_sum(float v) {
    v += __shfl_xor_sync(0xFFFFFFFFu, v, 16);
    v += __shfl_xor_sync(0xFFFFFFFFu, v, 8);
    v += __shfl_xor_sync(0xFFFFFFFFu, v, 4);
    v += __shfl_xor_sync(0xFFFFFFFFu, v, 2);
    v += __shfl_xor_sync(0xFFFFFFFFu, v, 1);
    return v;
}
__device__ __forceinline__ float warp_max(float v) {
    v = fmaxf(v, __shfl_xor_sync(0xFFFFFFFFu, v, 16));
    v = fmaxf(v, __shfl_xor_sync(0xFFFFFFFFu, v, 8));
    v = fmaxf(v, __shfl_xor_sync(0xFFFFFFFFu, v, 4));
    v = fmaxf(v, __shfl_xor_sync(0xFFFFFFFFu, v, 2));
    v = fmaxf(v, __shfl_xor_sync(0xFFFFFFFFu, v, 1));
    return v;
}

__global__ void __launch_bounds__(256) k2_attn(
    const float* __restrict__ spec,
    const float* __restrict__ vo,  const float* __restrict__ vc,
    const float* __restrict__ Wl1, const float* __restrict__ bl1,
    const float* __restrict__ Wac, const float* __restrict__ bac,
    const float* __restrict__ Wlc, const float* __restrict__ blc,
    float* __restrict__ out)
{
    const int tok = blockIdx.x;
    const int b   = tok >> 10;
    const int t   = tok & (TSEQ - 1);
    const int tid = threadIdx.x;
    const int warp = tid >> 5;
    const int lane = tid & 31;

    __shared__ float sc[64];
    __shared__ float aw[64];
    __shared__ float wsum[NBINS];
    __shared__ float x[2 * OUTF];     // [feat(88), onset(88)]
    __shared__ float gc[MODEL];
    __shared__ float part[256];

    // Per-warp register copies of g_onset and v_o (each warp redundantly; L1-cached)
    float gr[4], vr[4];
    #pragma unroll
    for (int mi = 0; mi < 4; mi++) {
        gr[mi] = g_go[(size_t)tok * MODEL + lane + 32 * mi];
        vr[mi] = vo[lane + 32 * mi];
    }
    if (tid < OUTF)
        x[tid] = out[FEAT_OFF + (size_t)tok * OUTF + tid];

    // ---- Onset attention scores ----
    for (int w = warp; w < WIN; w += 8) {
        int tp = t + w - WSZ;
        bool valid = ((unsigned)tp < (unsigned)TSEQ);
        const float* up = g_uo + (size_t)(b * TSEQ + tp) * MODEL;
        float p = 0.f;
        #pragma unroll
        for (int mi = 0; mi < 4; mi++) {
            float u = valid ? up[lane + 32 * mi] : 0.f;
            p += vr[mi] * tanh_fast(gr[mi] + u);
        }
        p = warp_sum(p);
        if (lane == 0) sc[w] = p;
    }
    __syncthreads();

    // ---- Softmax (warp 0), write a_onset ----
    if (warp == 0) {
        float s0 = (lane < WIN) ? sc[lane] : -1e30f;
        float s1 = (lane + 32 < WIN) ? sc[lane + 32] : -1e30f;
        float mx = warp_max(fmaxf(s0, s1));
        float e0 = (lane < WIN) ? __expf(s0 - mx) : 0.f;
        float e1 = (lane + 32 < WIN) ? __expf(s1 - mx) : 0.f;
        float inv = 1.f / warp_sum(e0 + e1);
        if (lane < WIN) {
            float a = e0 * inv;
            aw[lane] = a;
            out[AONSET_OFF + (size_t)tok * WIN + lane] = a;
        }
        if (lane + 32 < WIN) {
            float a = e1 * inv;
            aw[lane + 32] = a;
            out[AONSET_OFF + (size_t)tok * WIN + lane + 32] = a;
        }
    }
    __syncthreads();

    // ---- weighted_o ----
    if (tid < NBINS) {
        float acc = 0.f;
        #pragma unroll 4
        for (int w = 0; w < WIN; w++) {
            int tp = t + w - WSZ;
            if ((unsigned)tp < (unsigned)TSEQ)
                acc += aw[w] * spec[(size_t)(b * TSEQ + tp) * NBINS + tid];
        }
        wsum[tid] = acc;
    }
    __syncthreads();

    // ---- onset_pred (2-way k-split over 176 threads) ----
    if (tid < 176) {
        int col = (tid < 88) ? tid : tid - 88;
        int k0  = (tid < 88) ? 0 : 115;
        int k1  = (tid < 88) ? 115 : 229;
        float s = 0.f;
        #pragma unroll 4
        for (int k = k0; k < k1; k++)
            s += wsum[k] * Wl1[k * OUTF + col];
        part[tid] = s;
    }
    __syncthreads();
    if (tid < OUTF) {
        float o = sigmoid_fast(bl1[tid] + part[tid] + part[tid + 88]);
        out[ONSET_OFF + (size_t)tok * OUTF + tid] = o;
        x[OUTF + tid] = o;
    }
    __syncthreads();

    // ---- g_c = x @ Wac[0:176] + bac  (2-way k-split over all 256 threads) ----
    {
        int col = tid & 127;
        int k0  = (tid >> 7) * 88;
        float s = 0.f;
        #pragma unroll 4
        for (int k = k0; k < k0 + 88; k++)
            s += x[k] * Wac[k * MODEL + col];
        part[tid] = s;
    }
    __syncthreads();
    if (tid < MODEL)
        gc[tid] = part[tid] + part[tid + 128] + bac[tid];
    __syncthreads();

    // ---- Combine attention scores ----
    #pragma unroll
    for (int mi = 0; mi < 4; mi++) {
        gr[mi] = gc[lane + 32 * mi];
        vr[mi] = vc[lane + 32 * mi];
    }
    for (int w = warp; w < WIN; w += 8) {
        int tp = t + w - WSZ;
        bool valid = ((unsigned)tp < (unsigned)TSEQ);
        const float* up = g_uc + (size_t)(b * TSEQ + tp) * MODEL;
        float p = 0.f;
        #pragma unroll
        for (int mi = 0; mi < 4; mi++) {
            float u = valid ? up[lane + 32 * mi] : 0.f;
            p += vr[mi] * tanh_fast(gr[mi] + u);
        }
        p = warp_sum(p);
        if (lane == 0) sc[w] = p;
    }
    __syncthreads();

    // ---- Softmax (warp 0), write a_frame ----
    if (warp == 0) {
        float s0 = (lane < WIN) ? sc[lane] : -1e30f;
        float s1 = (lane + 32 < WIN) ? sc[lane + 32] : -1e30f;
        float mx = warp_max(fmaxf(s0, s1));
        float e0 = (lane < WIN) ? __expf(s0 - mx) : 0.f;
        float e1 = (lane + 32 < WIN) ? __expf(s1 - mx) : 0.f;
        float inv = 1.f / warp_sum(e0 + e1);
        if (lane < WIN) {
            float a = e0 * inv;
            aw[lane] = a;
            out[AFRAME_OFF + (size_t)tok * WIN + lane] = a;
        }
        if (lane + 32 < WIN) {
            float a = e1 * inv;
            aw[lane + 32] = a;
            out[AFRAME_OFF + (size_t)tok * WIN + lane + 32] = a;
        }
    }
    __syncthreads();

    // ---- weighted_c ----
    if (tid < NBINS) {
        float acc = 0.f;
        #pragma unroll 4
        for (int w = 0; w < WIN; w++) {
            int tp = t + w - WSZ;
            if ((unsigned)tp < (unsigned)TSEQ)
                acc += aw[w] * spec[(size_t)(b * TSEQ + tp) * NBINS + tid];
        }
        wsum[tid] = acc;
    }
    __syncthreads();

    // ---- frame_pred = sigmoid([x, weighted_c] @ Wlc + blc)  (2-way split) ----
    if (tid < 176) {
        int col = (tid < 88) ? tid : tid - 88;
        float s = 0.f;
        if (tid < 88) {
            #pragma unroll 4
            for (int k = 0; k < 2 * OUTF; k++)
                s += x[k] * Wlc[k * OUTF + col];
        } else {
            #pragma unroll 4
            for (int k = 0; k < NBINS; k++)
                s += wsum[k] * Wlc[(2 * OUTF + k) * OUTF + col];
        }
        part[tid] = s;
    }
    __syncthreads();
    if (tid < OUTF)
        out[FRAME_OFF + (size_t)tok * OUTF + tid] =
            sigmoid_fast(blc[tid] + part[tid] + part[tid + 88]);
}

extern "C" void kernel_launch(void* const* d_in, const int* in_sizes, int n_in,
                              void* d_out, int out_size)
{
    const float* spec = (const float*)d_in[0];
    const float* Wf   = (const float*)d_in[1];
    const float* bf   = (const float*)d_in[2];
    const float* Wao  = (const float*)d_in[3];
    const float* bao  = (const float*)d_in[4];
    const float* vo   = (const float*)d_in[5];
    const float* Wl1  = (const float*)d_in[6];
    const float* bl1  = (const float*)d_in[7];
    const float* Wac  = (const float*)d_in[8];
    const float* bac  = (const float*)d_in[9];
    const float* vc   = (const float*)d_in[10];
    const float* Wlc  = (const float*)d_in[11];
    const float* blc  = (const float*)d_in[12];
    float* out = (float*)d_out;

    k1_proj<<<NTOK / K1_TT, 512>>>(spec, Wf, bf, Wao, bao, Wac, out);
    k2_attn<<<NTOK, 256>>>(spec, vo, vc, Wl1, bl1, Wac, bac, Wlc, blc, out);
}

// round 3
// speedup vs baseline: 2.0000x; 1.8859x over previous
#include <cuda_runtime.h>
#include <math.h>

#define NBINS 229
#define OUTF  88
#define MODEL 128
#define WSZ   30
#define WIN   61
#define TSEQ  1024
#define NTOK  4096
#define TPAD  1084            // 30 + 1024 + 30
#define PSROW 232             // padded spec row (58 float4)

// Output layout (floats): frame_pred, a_frame, onset_pred, a_onset, feat_pred
#define FRAME_OFF  0
#define AFRAME_OFF (NTOK*OUTF)
#define ONSET_OFF  (AFRAME_OFF + NTOK*WIN)
#define AONSET_OFF (ONSET_OFF + NTOK*OUTF)
#define FEAT_OFF   (AONSET_OFF + NTOK*WIN)

// Scratch
__device__ float spec_pad[4 * TPAD * PSROW];   // padded + guarded spec
__device__ float g_go[NTOK * MODEL];           // g_onset (bias included)
__device__ float g_uo[4 * TPAD * MODEL];       // u_onset, guarded
__device__ float g_uc[4 * TPAD * MODEL];       // u_combine, guarded
__device__ float g_gc[NTOK * MODEL];           // g_combine
__device__ float wo_sc[NTOK * PSROW];          // weighted_o (padded rows)
__device__ float wc_sc[NTOK * PSROW];          // weighted_c (padded rows)

__device__ __forceinline__ float tanh_fast(float x) {
    float y; asm("tanh.approx.f32 %0, %1;" : "=f"(y) : "f"(x)); return y;
}
__device__ __forceinline__ float sigmoid_fast(float x) {
    return 1.f / (1.f + __expf(-x));
}
__device__ __forceinline__ float warp_sum(float v) {
    v += __shfl_xor_sync(0xFFFFFFFFu, v, 16);
    v += __shfl_xor_sync(0xFFFFFFFFu, v, 8);
    v += __shfl_xor_sync(0xFFFFFFFFu, v, 4);
    v += __shfl_xor_sync(0xFFFFFFFFu, v, 2);
    v += __shfl_xor_sync(0xFFFFFFFFu, v, 1);
    return v;
}
__device__ __forceinline__ float warp_max(float v) {
    v = fmaxf(v, __shfl_xor_sync(0xFFFFFFFFu, v, 16));
    v = fmaxf(v, __shfl_xor_sync(0xFFFFFFFFu, v, 8));
    v = fmaxf(v, __shfl_xor_sync(0xFFFFFFFFu, v, 4));
    v = fmaxf(v, __shfl_xor_sync(0xFFFFFFFFu, v, 2));
    v = fmaxf(v, __shfl_xor_sync(0xFFFFFFFFu, v, 1));
    return v;
}

// ---------------------------------------------------------------------------
// k0: build padded spec (+zero guards), zero guard rows of u_o/u_c
// ---------------------------------------------------------------------------
__global__ void k0_prep(const float* __restrict__ spec)
{
    const int r  = blockIdx.x;          // 0 .. 4*TPAD-1
    const int b  = r / TPAD;
    const int tp = r - b * TPAD;
    const int tid = threadIdx.x;        // 64
    if (tp < WSZ || tp >= WSZ + TSEQ) {
        float4 z = make_float4(0.f, 0.f, 0.f, 0.f);
        if (tid < 58) ((float4*)spec_pad)[(size_t)r * 58 + tid] = z;
        if (tid < 32) {
            ((float4*)g_uo)[(size_t)r * 32 + tid] = z;
            ((float4*)g_uc)[(size_t)r * 32 + tid] = z;
        }
    } else {
        const int t = tp - WSZ;
        const float* src = spec + (size_t)(b * TSEQ + t) * NBINS;
        float* dst = spec_pad + (size_t)r * PSROW;
        for (int i = tid; i < NBINS; i += 64) dst[i] = src[i];
        if (tid < 3) dst[NBINS + tid] = 0.f;
    }
}

// ---------------------------------------------------------------------------
// k1: fused projection GEMM  [NTOK x 229] @ [229 x 472]
// ---------------------------------------------------------------------------
#define K1_TT 16
__global__ void __launch_bounds__(512) k1_proj(
    const float* __restrict__ spec,
    const float* __restrict__ Wf,  const float* __restrict__ bf,
    const float* __restrict__ Wao, const float* __restrict__ bao,
    const float* __restrict__ Wac,
    float* __restrict__ out)
{
    __shared__ float sh[NBINS][20];
    const int tok0 = blockIdx.x * K1_TT;

    for (int idx = threadIdx.x; idx < NBINS * K1_TT; idx += blockDim.x) {
        int tt = idx / NBINS;
        int k  = idx - tt * NBINS;
        sh[k][tt] = spec[(size_t)(tok0 + tt) * NBINS + k];
    }
    __syncthreads();

    const int j = threadIdx.x;
    if (j >= 472) return;

    const float* wp;
    int stride;
    float bias = 0.f;
    if (j < 88)       { wp = Wf + j;                        stride = OUTF;  bias = bf[j]; }
    else if (j < 216) { wp = Wao + (j - 88);                stride = MODEL; bias = bao[j - 88]; }
    else if (j < 344) { wp = Wao + NBINS*MODEL + (j - 216); stride = MODEL; }
    else              { wp = Wac + 176*MODEL  + (j - 344);  stride = MODEL; }

    float acc[K1_TT];
    #pragma unroll
    for (int i = 0; i < K1_TT; i++) acc[i] = 0.f;

    #pragma unroll 4
    for (int k = 0; k < NBINS; k++) {
        float w = *wp; wp += stride;
        const float4* row = reinterpret_cast<const float4*>(&sh[k][0]);
        float4 s0 = row[0], s1 = row[1], s2 = row[2], s3 = row[3];
        acc[0]  += s0.x * w; acc[1]  += s0.y * w; acc[2]  += s0.z * w; acc[3]  += s0.w * w;
        acc[4]  += s1.x * w; acc[5]  += s1.y * w; acc[6]  += s1.z * w; acc[7]  += s1.w * w;
        acc[8]  += s2.x * w; acc[9]  += s2.y * w; acc[10] += s2.z * w; acc[11] += s2.w * w;
        acc[12] += s3.x * w; acc[13] += s3.y * w; acc[14] += s3.z * w; acc[15] += s3.w * w;
    }

    if (j < 88) {
        #pragma unroll
        for (int tt = 0; tt < K1_TT; tt++)
            out[FEAT_OFF + (size_t)(tok0 + tt) * OUTF + j] = acc[tt] + bias;
    } else if (j < 216) {
        int m = j - 88;
        #pragma unroll
        for (int tt = 0; tt < K1_TT; tt++)
            g_go[(size_t)(tok0 + tt) * MODEL + m] = acc[tt] + bias;
    } else if (j < 344) {
        int m = j - 216;
        #pragma unroll
        for (int tt = 0; tt < K1_TT; tt++) {
            int tok = tok0 + tt;
            int row = (tok >> 10) * TPAD + WSZ + (tok & (TSEQ - 1));
            g_uo[(size_t)row * MODEL + m] = acc[tt];
        }
    } else {
        int m = j - 344;
        #pragma unroll
        for (int tt = 0; tt < K1_TT; tt++) {
            int tok = tok0 + tt;
            int row = (tok >> 10) * TPAD + WSZ + (tok & (TSEQ - 1));
            g_uc[(size_t)row * MODEL + m] = acc[tt];
        }
    }
}

// ---------------------------------------------------------------------------
// k_attn: per-token attention: scores + softmax + weighted window sum.
// Used for both onset and combine passes (pointer-parameterized).
// ---------------------------------------------------------------------------
__global__ void __launch_bounds__(256) k_attn(
    const float* __restrict__ gv,     // [NTOK][128]
    const float* __restrict__ u_pad,  // [4][TPAD][128] guarded
    const float* __restrict__ vvec,   // [128]
    float* __restrict__ a_out,        // [NTOK][61]
    float* __restrict__ w_out)        // [NTOK][PSROW]
{
    const int tok  = blockIdx.x;
    const int b    = tok >> 10;
    const int t    = tok & (TSEQ - 1);
    const int tid  = threadIdx.x;
    const int warp = tid >> 5;
    const int lane = tid & 31;

    __shared__ float sc[64];
    __shared__ float aw[64];

    const float4 g4 = *(const float4*)(gv   + (size_t)tok * MODEL + lane * 4);
    const float4 v4 = *(const float4*)(vvec + lane * 4);
    const float4* ubase = (const float4*)(u_pad + (size_t)(b * TPAD + t) * MODEL) + lane;

    #pragma unroll 2
    for (int w = warp; w < WIN; w += 8) {
        float4 u4 = ubase[(size_t)w * 32];
        float p = v4.x * tanh_fast(g4.x + u4.x)
                + v4.y * tanh_fast(g4.y + u4.y)
                + v4.z * tanh_fast(g4.z + u4.z)
                + v4.w * tanh_fast(g4.w + u4.w);
        p = warp_sum(p);
        if (lane == 0) sc[w] = p;
    }
    __syncthreads();

    if (warp == 0) {
        float s0 = (lane < WIN) ? sc[lane] : -1e30f;
        float s1 = (lane + 32 < WIN) ? sc[lane + 32] : -1e30f;
        float mx = warp_max(fmaxf(s0, s1));
        float e0 = (lane < WIN) ? __expf(s0 - mx) : 0.f;
        float e1 = (lane + 32 < WIN) ? __expf(s1 - mx) : 0.f;
        float inv = 1.f / warp_sum(e0 + e1);
        if (lane < WIN) {
            float a = e0 * inv;
            aw[lane] = a;
            a_out[(size_t)tok * WIN + lane] = a;
        }
        if (lane + 32 < WIN) {
            float a = e1 * inv;
            aw[lane + 32] = a;
            a_out[(size_t)tok * WIN + lane + 32] = a;
        }
    }
    __syncthreads();

    // weighted window sum: 58 float4 columns
    if (tid < 58) {
        const float4* sp = (const float4*)spec_pad + (size_t)(b * TPAD + t) * 58 + tid;
        float4 acc = make_float4(0.f, 0.f, 0.f, 0.f);
        #pragma unroll 4
        for (int w = 0; w < WIN; w++) {
            float a = aw[w];
            float4 s = sp[(size_t)w * 58];
            acc.x += a * s.x; acc.y += a * s.y; acc.z += a * s.z; acc.w += a * s.w;
        }
        ((float4*)w_out)[(size_t)tok * 58 + tid] = acc;
    }
}

// ---------------------------------------------------------------------------
// k2b: 16 tokens/block. onset_pred = sigmoid(wo @ Wl1 + b), then
//      g_c = [feat,onset] @ Wac_top + bac.
// Shared A rows: [0..228]=wo, [229..316]=feat, [317..404]=onset
// ---------------------------------------------------------------------------
__global__ void __launch_bounds__(512) k2b_onset_gc(
    const float* __restrict__ Wl1, const float* __restrict__ bl1,
    const float* __restrict__ Wac, const float* __restrict__ bac,
    float* __restrict__ out)
{
    __shared__ float A[405][16];
    __shared__ float part[5632];
    const int tok0 = blockIdx.x * 16;
    const int tid = threadIdx.x;

    // stage weighted_o
    for (int idx = tid; idx < 16 * 58; idx += 512) {
        int tt = idx / 58, c = idx - tt * 58;
        float4 v = ((const float4*)wo_sc)[(size_t)(tok0 + tt) * 58 + c];
        int r = c * 4;
        A[r][tt] = v.x;
        if (r + 1 < NBINS) { A[r+1][tt] = v.y; A[r+2][tt] = v.z; A[r+3][tt] = v.w; }
    }
    // stage feat
    for (int idx = tid; idx < 16 * 22; idx += 512) {
        int tt = idx / 22, c = idx - tt * 22;
        float4 f = ((const float4*)(out + FEAT_OFF))[(size_t)(tok0 + tt) * 22 + c];
        int r = 229 + c * 4;
        A[r][tt] = f.x; A[r+1][tt] = f.y; A[r+2][tt] = f.z; A[r+3][tt] = f.w;
    }
    __syncthreads();

    // onset GEMM: 4 k-splits x 88 cols
    if (tid < 352) {
        int s = tid / 88, j = tid - s * 88;
        int ks = (s * NBINS) >> 2, ke = ((s + 1) * NBINS) >> 2;
        float acc[16];
        #pragma unroll
        for (int i = 0; i < 16; i++) acc[i] = 0.f;
        for (int k = ks; k < ke; k++) {
            float wv = Wl1[k * OUTF + j];
            const float4* row = (const float4*)A[k];
            float4 a0 = row[0], a1 = row[1], a2 = row[2], a3 = row[3];
            acc[0]  += a0.x*wv; acc[1]  += a0.y*wv; acc[2]  += a0.z*wv; acc[3]  += a0.w*wv;
            acc[4]  += a1.x*wv; acc[5]  += a1.y*wv; acc[6]  += a1.z*wv; acc[7]  += a1.w*wv;
            acc[8]  += a2.x*wv; acc[9]  += a2.y*wv; acc[10] += a2.z*wv; acc[11] += a2.w*wv;
            acc[12] += a3.x*wv; acc[13] += a3.y*wv; acc[14] += a3.z*wv; acc[15] += a3.w*wv;
        }
        #pragma unroll
        for (int ttt = 0; ttt < 16; ttt++) part[ttt * 352 + tid] = acc[ttt];
    }
    __syncthreads();
    for (int e = tid; e < OUTF * 16; e += 512) {
        int tt = e / OUTF, j = e - tt * OUTF;
        float sres = bl1[j] + part[tt*352 + j] + part[tt*352 + 88 + j]
                   + part[tt*352 + 176 + j] + part[tt*352 + 264 + j];
        float o = sigmoid_fast(sres);
        out[ONSET_OFF + (size_t)(tok0 + tt) * OUTF + j] = o;
        A[317 + j][tt] = o;
    }
    __syncthreads();

    // g_c GEMM: 2 k-splits x 128 cols
    if (tid < 256) {
        int s = tid >> 7, j = tid & 127;
        float acc[16];
        #pragma unroll
        for (int i = 0; i < 16; i++) acc[i] = 0.f;
        for (int k = s * 88; k < s * 88 + 88; k++) {
            float wv = Wac[k * MODEL + j];
            const float4* row = (const float4*)A[229 + k];
            float4 a0 = row[0], a1 = row[1], a2 = row[2], a3 = row[3];
            acc[0]  += a0.x*wv; acc[1]  += a0.y*wv; acc[2]  += a0.z*wv; acc[3]  += a0.w*wv;
            acc[4]  += a1.x*wv; acc[5]  += a1.y*wv; acc[6]  += a1.z*wv; acc[7]  += a1.w*wv;
            acc[8]  += a2.x*wv; acc[9]  += a2.y*wv; acc[10] += a2.z*wv; acc[11] += a2.w*wv;
            acc[12] += a3.x*wv; acc[13] += a3.y*wv; acc[14] += a3.z*wv; acc[15] += a3.w*wv;
        }
        #pragma unroll
        for (int ttt = 0; ttt < 16; ttt++) part[ttt * 256 + tid] = acc[ttt];
    }
    __syncthreads();
    for (int e = tid; e < MODEL * 16; e += 512) {
        int tt = e >> 7, j = e & 127;
        g_gc[(size_t)(tok0 + tt) * MODEL + j] =
            bac[j] + part[tt*256 + j] + part[tt*256 + 128 + j];
    }
}

// ---------------------------------------------------------------------------
// k2d: 16 tokens/block. frame_pred = sigmoid([feat,onset,wc] @ Wlc + blc)
// A rows: [0..87]=feat, [88..175]=onset, [176..404]=wc
// ---------------------------------------------------------------------------
__global__ void __launch_bounds__(512) k2d_frame(
    const float* __restrict__ Wlc, const float* __restrict__ blc,
    float* __restrict__ out)
{
    __shared__ float A[405][16];
    __shared__ float part[5632];
    const int tok0 = blockIdx.x * 16;
    const int tid = threadIdx.x;

    for (int idx = tid; idx < 16 * 22; idx += 512) {
        int tt = idx / 22, c = idx - tt * 22;
        float4 f = ((const float4*)(out + FEAT_OFF))[(size_t)(tok0 + tt) * 22 + c];
        float4 o = ((const float4*)(out + ONSET_OFF))[(size_t)(tok0 + tt) * 22 + c];
        int r = c * 4;
        A[r][tt] = f.x; A[r+1][tt] = f.y; A[r+2][tt] = f.z; A[r+3][tt] = f.w;
        A[88+r][tt] = o.x; A[88+r+1][tt] = o.y; A[88+r+2][tt] = o.z; A[88+r+3][tt] = o.w;
    }
    for (int idx = tid; idx < 16 * 58; idx += 512) {
        int tt = idx / 58, c = idx - tt * 58;
        float4 v = ((const float4*)wc_sc)[(size_t)(tok0 + tt) * 58 + c];
        int r = 176 + c * 4;
        A[r][tt] = v.x;
        if (c * 4 + 1 < NBINS) { A[r+1][tt] = v.y; A[r+2][tt] = v.z; A[r+3][tt] = v.w; }
    }
    __syncthreads();

    if (tid < 352) {
        int s = tid / 88, j = tid - s * 88;
        int ks = (s * 405) >> 2, ke = ((s + 1) * 405) >> 2;
        float acc[16];
        #pragma unroll
        for (int i = 0; i < 16; i++) acc[i] = 0.f;
        for (int k = ks; k < ke; k++) {
            float wv = Wlc[k * OUTF + j];
            const float4* row = (const float4*)A[k];
            float4 a0 = row[0], a1 = row[1], a2 = row[2], a3 = row[3];
            acc[0]  += a0.x*wv; acc[1]  += a0.y*wv; acc[2]  += a0.z*wv; acc[3]  += a0.w*wv;
            acc[4]  += a1.x*wv; acc[5]  += a1.y*wv; acc[6]  += a1.z*wv; acc[7]  += a1.w*wv;
            acc[8]  += a2.x*wv; acc[9]  += a2.y*wv; acc[10] += a2.z*wv; acc[11] += a2.w*wv;
            acc[12] += a3.x*wv; acc[13] += a3.y*wv; acc[14] += a3.z*wv; acc[15] += a3.w*wv;
        }
        #pragma unroll
        for (int ttt = 0; ttt < 16; ttt++) part[ttt * 352 + tid] = acc[ttt];
    }
    __syncthreads();
    for (int e = tid; e < OUTF * 16; e += 512) {
        int tt = e / OUTF, j = e - tt * OUTF;
        float sres = blc[j] + part[tt*352 + j] + part[tt*352 + 88 + j]
                   + part[tt*352 + 176 + j] + part[tt*352 + 264 + j];
        out[FRAME_OFF + (size_t)(tok0 + tt) * OUTF + j] = sigmoid_fast(sres);
    }
}

extern "C" void kernel_launch(void* const* d_in, const int* in_sizes, int n_in,
                              void* d_out, int out_size)
{
    const float* spec = (const float*)d_in[0];
    const float* Wf   = (const float*)d_in[1];
    const float* bf   = (const float*)d_in[2];
    const float* Wao  = (const float*)d_in[3];
    const float* bao  = (const float*)d_in[4];
    const float* vo   = (const float*)d_in[5];
    const float* Wl1  = (const float*)d_in[6];
    const float* bl1  = (const float*)d_in[7];
    const float* Wac  = (const float*)d_in[8];
    const float* bac  = (const float*)d_in[9];
    const float* vc   = (const float*)d_in[10];
    const float* Wlc  = (const float*)d_in[11];
    const float* blc  = (const float*)d_in[12];
    float* out = (float*)d_out;

    float *p_go, *p_uo, *p_uc, *p_gc, *p_wo, *p_wc;
    cudaGetSymbolAddress((void**)&p_go, g_go);
    cudaGetSymbolAddress((void**)&p_uo, g_uo);
    cudaGetSymbolAddress((void**)&p_uc, g_uc);
    cudaGetSymbolAddress((void**)&p_gc, g_gc);
    cudaGetSymbolAddress((void**)&p_wo, wo_sc);
    cudaGetSymbolAddress((void**)&p_wc, wc_sc);

    k0_prep<<<4 * TPAD, 64>>>(spec);
    k1_proj<<<NTOK / K1_TT, 512>>>(spec, Wf, bf, Wao, bao, Wac, out);
    k_attn<<<NTOK, 256>>>(p_go, p_uo, vo, out + AONSET_OFF, p_wo);
    k2b_onset_gc<<<NTOK / 16, 512>>>(Wl1, bl1, Wac, bac, out);
    k_attn<<<NTOK, 256>>>(p_gc, p_uc, vc, out + AFRAME_OFF, p_wc);
    k2d_frame<<<NTOK / 16, 512>>>(Wlc, blc, out);
}

// round 4
// speedup vs baseline: 2.3532x; 1.1766x over previous
#include <cuda_runtime.h>
#include <math.h>

#define NBINS 229
#define OUTF  88
#define MODEL 128
#define WSZ   30
#define WIN   61
#define TSEQ  1024
#define NTOK  4096
#define TPAD  1084            // 30 + 1024 + 30
#define PCOLS 176             // P1(88) | P2(88)

// Output layout (floats): frame_pred, a_frame, onset_pred, a_onset, feat_pred
#define FRAME_OFF  0
#define AFRAME_OFF (NTOK*OUTF)
#define ONSET_OFF  (AFRAME_OFF + NTOK*WIN)
#define AONSET_OFF (ONSET_OFF + NTOK*OUTF)
#define FEAT_OFF   (AONSET_OFF + NTOK*WIN)

// Scratch (__device__ globals; no allocation allowed)
__device__ float g_go[NTOK * MODEL];           // g_onset (bias included)
__device__ float g_uo[4 * TPAD * MODEL];       // u_onset, zero-guarded
__device__ float g_uc[4 * TPAD * MODEL];       // u_combine, zero-guarded
__device__ float g_p12[4 * TPAD * PCOLS];      // P1|P2 = spec@Wl1 | spec@Wlc_bot, guarded
__device__ float g_gc[NTOK * MODEL];           // g_combine
__device__ float g_xl[NTOK * OUTF];            // [feat,onset]@Wlc_top + blc

__device__ __forceinline__ float tanh_fast(float x) {
    float y; asm("tanh.approx.f32 %0, %1;" : "=f"(y) : "f"(x)); return y;
}
__device__ __forceinline__ float sigmoid_fast(float x) {
    return 1.f / (1.f + __expf(-x));
}
__device__ __forceinline__ unsigned long long pkf2(float lo, float hi) {
    unsigned long long r;
    asm("mov.b64 %0, {%1, %2};" : "=l"(r) : "f"(lo), "f"(hi));
    return r;
}
__device__ __forceinline__ void fma2(unsigned long long& acc,
                                     unsigned long long a, unsigned long long b) {
    asm("fma.rn.f32x2 %0, %1, %2, %0;" : "+l"(acc) : "l"(a), "l"(b));
}
__device__ __forceinline__ float2 upk(unsigned long long v) {
    float2 r;
    asm("mov.b64 {%0, %1}, %2;" : "=f"(r.x), "=f"(r.y) : "l"(v));
    return r;
}
__device__ __forceinline__ float warp_sum(float v) {
    v += __shfl_xor_sync(0xFFFFFFFFu, v, 16);
    v += __shfl_xor_sync(0xFFFFFFFFu, v, 8);
    v += __shfl_xor_sync(0xFFFFFFFFu, v, 4);
    v += __shfl_xor_sync(0xFFFFFFFFu, v, 2);
    v += __shfl_xor_sync(0xFFFFFFFFu, v, 1);
    return v;
}
__device__ __forceinline__ float warp_max(float v) {
    v = fmaxf(v, __shfl_xor_sync(0xFFFFFFFFu, v, 16));
    v = fmaxf(v, __shfl_xor_sync(0xFFFFFFFFu, v, 8));
    v = fmaxf(v, __shfl_xor_sync(0xFFFFFFFFu, v, 4));
    v = fmaxf(v, __shfl_xor_sync(0xFFFFFFFFu, v, 2));
    v = fmaxf(v, __shfl_xor_sync(0xFFFFFFFFu, v, 1));
    return v;
}

// ---------------------------------------------------------------------------
// k0z: zero guard rows of u_o / u_c / P12 (60 rows per batch)
// ---------------------------------------------------------------------------
__global__ void k0z()
{
    const int i = blockIdx.x;            // 0..239
    const int b = i / 60;
    const int r = i - b * 60;
    const int tp = (r < WSZ) ? r : (WSZ + TSEQ + r - WSZ);  // [0,30) U [1054,1084)
    const size_t row = (size_t)b * TPAD + tp;
    const int tid = threadIdx.x;         // 64
    float4 z = make_float4(0.f, 0.f, 0.f, 0.f);
    if (tid < 32) {
        ((float4*)g_uo)[row * 32 + tid] = z;
        ((float4*)g_uc)[row * 32 + tid] = z;
    }
    if (tid < 44) ((float4*)g_p12)[row * 44 + tid] = z;
}

// ---------------------------------------------------------------------------
// k1: mega projection GEMM  [NTOK x 229] @ [229 x 648]
//   cols   0.. 87 : feat_pred (+bf)   -> out FEAT
//   cols  88..215 : g_o      (+bao)   -> g_go
//   cols 216..343 : u_o               -> g_uo (guard-padded rows)
//   cols 344..471 : u_c               -> g_uc
//   cols 472..559 : P1 = spec@Wl1     -> g_p12[:, 0:88]
//   cols 560..647 : P2 = spec@Wlc_bot -> g_p12[:, 88:176]
// ---------------------------------------------------------------------------
#define K1_TT 16
__global__ void __launch_bounds__(672) k1_proj(
    const float* __restrict__ spec,
    const float* __restrict__ Wf,  const float* __restrict__ bf,
    const float* __restrict__ Wao, const float* __restrict__ bao,
    const float* __restrict__ Wac,
    const float* __restrict__ Wl1,
    const float* __restrict__ Wlc,
    float* __restrict__ out)
{
    __shared__ __align__(16) float sh[NBINS][20];
    const int tok0 = blockIdx.x * K1_TT;

    for (int idx = threadIdx.x; idx < NBINS * K1_TT; idx += 672) {
        int tt = idx / NBINS;
        int k  = idx - tt * NBINS;
        sh[k][tt] = spec[(size_t)(tok0 + tt) * NBINS + k];
    }
    __syncthreads();

    const int j = threadIdx.x;
    if (j >= 648) return;

    const float* wp;
    int stride;
    if (j < 88)       { wp = Wf + j;                          stride = OUTF;  }
    else if (j < 216) { wp = Wao + (j - 88);                  stride = MODEL; }
    else if (j < 344) { wp = Wao + NBINS*MODEL + (j - 216);   stride = MODEL; }
    else if (j < 472) { wp = Wac + 176*MODEL  + (j - 344);    stride = MODEL; }
    else if (j < 560) { wp = Wl1 + (j - 472);                 stride = OUTF;  }
    else              { wp = Wlc + 176*OUTF   + (j - 560);    stride = OUTF;  }

    unsigned long long acc[8];
    #pragma unroll
    for (int p = 0; p < 8; p++) acc[p] = 0ull;

    #pragma unroll 4
    for (int k = 0; k < NBINS; k++) {
        float w = *wp; wp += stride;
        unsigned long long ww = pkf2(w, w);
        const unsigned long long* row = (const unsigned long long*)&sh[k][0];
        #pragma unroll
        for (int p = 0; p < 8; p++) fma2(acc[p], row[p], ww);
    }

    float rv[16];
    #pragma unroll
    for (int p = 0; p < 8; p++) {
        float2 r = upk(acc[p]);
        rv[2*p] = r.x; rv[2*p+1] = r.y;
    }

    const int b    = tok0 >> 10;
    const size_t row0 = (size_t)b * TPAD + WSZ + (tok0 & (TSEQ - 1));

    if (j < 88) {
        float bias = bf[j];
        #pragma unroll
        for (int tt = 0; tt < K1_TT; tt++)
            out[FEAT_OFF + (size_t)(tok0 + tt) * OUTF + j] = rv[tt] + bias;
    } else if (j < 216) {
        int m = j - 88;
        float bias = bao[m];
        #pragma unroll
        for (int tt = 0; tt < K1_TT; tt++)
            g_go[(size_t)(tok0 + tt) * MODEL + m] = rv[tt] + bias;
    } else if (j < 344) {
        int m = j - 216;
        #pragma unroll
        for (int tt = 0; tt < K1_TT; tt++)
            g_uo[(row0 + tt) * MODEL + m] = rv[tt];
    } else if (j < 472) {
        int m = j - 344;
        #pragma unroll
        for (int tt = 0; tt < K1_TT; tt++)
            g_uc[(row0 + tt) * MODEL + m] = rv[tt];
    } else if (j < 560) {
        int m = j - 472;
        #pragma unroll
        for (int tt = 0; tt < K1_TT; tt++)
            g_p12[(row0 + tt) * PCOLS + m] = rv[tt];
    } else {
        int m = j - 560 + 88;
        #pragma unroll
        for (int tt = 0; tt < K1_TT; tt++)
            g_p12[(row0 + tt) * PCOLS + m] = rv[tt];
    }
}

// ---------------------------------------------------------------------------
// k_attn_fused: scores + softmax + 88-dim windowed P-sum + sigmoid output.
//   PER_TOKEN_ADD=false: addv = bl1[88]        (onset pass)
//   PER_TOKEN_ADD=true : addv = g_xl[NTOK][88] (combine pass)
// ---------------------------------------------------------------------------
template<bool PER_TOKEN_ADD>
__global__ void __launch_bounds__(256) k_attn_fused(
    const float* __restrict__ gv,     // [NTOK][128]
    const float* __restrict__ u_pad,  // [4][TPAD][128] guarded
    const float* __restrict__ vvec,   // [128]
    const float* __restrict__ addv,
    const float* __restrict__ ppad,   // g_p12
    int pcol,
    float* __restrict__ a_out,        // [NTOK][61]
    float* __restrict__ p_out)        // [NTOK][88]
{
    const int tok  = blockIdx.x;
    const int b    = tok >> 10;
    const int t    = tok & (TSEQ - 1);
    const int tid  = threadIdx.x;
    const int warp = tid >> 5;
    const int lane = tid & 31;

    __shared__ float sc[64];
    __shared__ float aw[64];

    const float4 g4 = *(const float4*)(gv   + (size_t)tok * MODEL + lane * 4);
    const float4 v4 = *(const float4*)(vvec + lane * 4);
    const float4* ubase = (const float4*)(u_pad + (size_t)(b * TPAD + t) * MODEL) + lane;

    #pragma unroll 2
    for (int w = warp; w < WIN; w += 8) {
        float4 u4 = ubase[(size_t)w * 32];
        float p = v4.x * tanh_fast(g4.x + u4.x)
                + v4.y * tanh_fast(g4.y + u4.y)
                + v4.z * tanh_fast(g4.z + u4.z)
                + v4.w * tanh_fast(g4.w + u4.w);
        p = warp_sum(p);
        if (lane == 0) sc[w] = p;
    }
    __syncthreads();

    if (warp == 0) {
        float s0 = (lane < WIN) ? sc[lane] : -1e30f;
        float s1 = (lane + 32 < WIN) ? sc[lane + 32] : -1e30f;
        float mx = warp_max(fmaxf(s0, s1));
        float e0 = (lane < WIN) ? __expf(s0 - mx) : 0.f;
        float e1 = (lane + 32 < WIN) ? __expf(s1 - mx) : 0.f;
        float inv = 1.f / warp_sum(e0 + e1);
        if (lane < WIN) {
            float a = e0 * inv;
            aw[lane] = a;
            a_out[(size_t)tok * WIN + lane] = a;
        }
        if (lane + 32 < WIN) {
            float a = e1 * inv;
            aw[lane + 32] = a;
            a_out[(size_t)tok * WIN + lane + 32] = a;
        }
    }
    __syncthreads();

    if (tid < OUTF) {
        const float* pp = ppad + (size_t)(b * TPAD + t) * PCOLS + pcol + tid;
        float acc = 0.f;
        #pragma unroll 61
        for (int w = 0; w < WIN; w++)
            acc += aw[w] * pp[(size_t)w * PCOLS];
        float addt = PER_TOKEN_ADD ? addv[(size_t)tok * OUTF + tid] : addv[tid];
        p_out[(size_t)tok * OUTF + tid] = sigmoid_fast(acc + addt);
    }
}

// ---------------------------------------------------------------------------
// k2b: 16 tokens/block. From x=[feat,onset] compute:
//   g_c = x @ Wac_top + bac   (128 cols)
//   xl  = x @ Wlc_top + blc   (88 cols)
// ---------------------------------------------------------------------------
__global__ void __launch_bounds__(224) k2b_gc_xl(
    const float* __restrict__ Wac, const float* __restrict__ bac,
    const float* __restrict__ Wlc, const float* __restrict__ blc,
    const float* __restrict__ out)
{
    __shared__ __align__(16) float A[176][16];
    const int tok0 = blockIdx.x * 16;
    const int tid = threadIdx.x;

    for (int idx = tid; idx < 176 * 16; idx += 224) {
        int tt = idx / 176, r = idx - tt * 176;
        float v = (r < 88)
            ? out[FEAT_OFF  + (size_t)(tok0 + tt) * OUTF + r]
            : out[ONSET_OFF + (size_t)(tok0 + tt) * OUTF + (r - 88)];
        A[r][tt] = v;
    }
    __syncthreads();

    if (tid >= 216) return;
    const int j = tid;
    const float* wp;
    int stride;
    if (j < 128) { wp = Wac + j;        stride = MODEL; }
    else         { wp = Wlc + (j-128);  stride = OUTF;  }

    unsigned long long acc[8];
    #pragma unroll
    for (int p = 0; p < 8; p++) acc[p] = 0ull;

    #pragma unroll 4
    for (int k = 0; k < 176; k++) {
        float w = *wp; wp += stride;
        unsigned long long ww = pkf2(w, w);
        const unsigned long long* row = (const unsigned long long*)&A[k][0];
        #pragma unroll
        for (int p = 0; p < 8; p++) fma2(acc[p], row[p], ww);
    }

    float rv[16];
    #pragma unroll
    for (int p = 0; p < 8; p++) {
        float2 r = upk(acc[p]);
        rv[2*p] = r.x; rv[2*p+1] = r.y;
    }

    if (j < 128) {
        float bias = bac[j];
        #pragma unroll
        for (int tt = 0; tt < 16; tt++)
            g_gc[(size_t)(tok0 + tt) * MODEL + j] = rv[tt] + bias;
    } else {
        int m = j - 128;
        float bias = blc[m];
        #pragma unroll
        for (int tt = 0; tt < 16; tt++)
            g_xl[(size_t)(tok0 + tt) * OUTF + m] = rv[tt] + bias;
    }
}

extern "C" void kernel_launch(void* const* d_in, const int* in_sizes, int n_in,
                              void* d_out, int out_size)
{
    const float* spec = (const float*)d_in[0];
    const float* Wf   = (const float*)d_in[1];
    const float* bf   = (const float*)d_in[2];
    const float* Wao  = (const float*)d_in[3];
    const float* bao  = (const float*)d_in[4];
    const float* vo   = (const float*)d_in[5];
    const float* Wl1  = (const float*)d_in[6];
    const float* bl1  = (const float*)d_in[7];
    const float* Wac  = (const float*)d_in[8];
    const float* bac  = (const float*)d_in[9];
    const float* vc   = (const float*)d_in[10];
    const float* Wlc  = (const float*)d_in[11];
    const float* blc  = (const float*)d_in[12];
    float* out = (float*)d_out;

    float *p_go, *p_uo, *p_uc, *p_gc, *p_p12, *p_xl;
    cudaGetSymbolAddress((void**)&p_go,  g_go);
    cudaGetSymbolAddress((void**)&p_uo,  g_uo);
    cudaGetSymbolAddress((void**)&p_uc,  g_uc);
    cudaGetSymbolAddress((void**)&p_gc,  g_gc);
    cudaGetSymbolAddress((void**)&p_p12, g_p12);
    cudaGetSymbolAddress((void**)&p_xl,  g_xl);

    k0z<<<240, 64>>>();
    k1_proj<<<NTOK / K1_TT, 672>>>(spec, Wf, bf, Wao, bao, Wac, Wl1, Wlc, out);
    k_attn_fused<false><<<NTOK, 256>>>(p_go, p_uo, vo, bl1, p_p12, 0,
                                       out + AONSET_OFF, out + ONSET_OFF);
    k2b_gc_xl<<<NTOK / 16, 224>>>(Wac, bac, Wlc, blc, out);
    k_attn_fused<true><<<NTOK, 256>>>(p_gc, p_uc, vc, p_xl, p_p12, 88,
                                      out + AFRAME_OFF, out + FRAME_OFF);
}

// round 5
// speedup vs baseline: 2.5299x; 1.0751x over previous
#include <cuda_runtime.h>
#include <math.h>

#define NBINS 229
#define OUTF  88
#define MODEL 128
#define WSZ   30
#define WIN   61
#define TSEQ  1024
#define NTOK  4096
#define TPAD  1084            // 30 + 1024 + 30
#define PCOLS 176             // P1(88) | P2(88)

// Output layout (floats): frame_pred, a_frame, onset_pred, a_onset, feat_pred
#define FRAME_OFF  0
#define AFRAME_OFF (NTOK*OUTF)
#define ONSET_OFF  (AFRAME_OFF + NTOK*WIN)
#define AONSET_OFF (ONSET_OFF + NTOK*OUTF)
#define FEAT_OFF   (AONSET_OFF + NTOK*WIN)

// Scratch (__device__ globals; zero-initialized at module load — guard rows
// of g_uo/g_uc/g_p12 are never written by any kernel, so they stay zero).
__device__ float g_go[NTOK * MODEL];           // g_onset (bias included)
__device__ float g_uo[4 * TPAD * MODEL];       // u_onset, zero-guarded
__device__ float g_uc[4 * TPAD * MODEL];       // u_combine, zero-guarded
__device__ float g_p12[4 * TPAD * PCOLS];      // P1|P2, zero-guarded
__device__ float g_gc[NTOK * MODEL];           // g_combine
__device__ float g_xl[NTOK * OUTF];            // [feat,onset]@Wlc_top + blc

__device__ __forceinline__ float tanh_fast(float x) {
    float y; asm("tanh.approx.f32 %0, %1;" : "=f"(y) : "f"(x)); return y;
}
__device__ __forceinline__ float sigmoid_fast(float x) {
    return 1.f / (1.f + __expf(-x));
}
__device__ __forceinline__ unsigned long long pkf2(float lo, float hi) {
    unsigned long long r;
    asm("mov.b64 %0, {%1, %2};" : "=l"(r) : "f"(lo), "f"(hi));
    return r;
}
__device__ __forceinline__ void fma2(unsigned long long& acc,
                                     unsigned long long a, unsigned long long b) {
    asm("fma.rn.f32x2 %0, %1, %2, %0;" : "+l"(acc) : "l"(a), "l"(b));
}
__device__ __forceinline__ float2 upk(unsigned long long v) {
    float2 r;
    asm("mov.b64 {%0, %1}, %2;" : "=f"(r.x), "=f"(r.y) : "l"(v));
    return r;
}
__device__ __forceinline__ float warp_sum(float v) {
    v += __shfl_xor_sync(0xFFFFFFFFu, v, 16);
    v += __shfl_xor_sync(0xFFFFFFFFu, v, 8);
    v += __shfl_xor_sync(0xFFFFFFFFu, v, 4);
    v += __shfl_xor_sync(0xFFFFFFFFu, v, 2);
    v += __shfl_xor_sync(0xFFFFFFFFu, v, 1);
    return v;
}
__device__ __forceinline__ float warp_max(float v) {
    v = fmaxf(v, __shfl_xor_sync(0xFFFFFFFFu, v, 16));
    v = fmaxf(v, __shfl_xor_sync(0xFFFFFFFFu, v, 8));
    v = fmaxf(v, __shfl_xor_sync(0xFFFFFFFFu, v, 4));
    v = fmaxf(v, __shfl_xor_sync(0xFFFFFFFFu, v, 2));
    v = fmaxf(v, __shfl_xor_sync(0xFFFFFFFFu, v, 1));
    return v;
}

// ---------------------------------------------------------------------------
// k1: mega projection GEMM  [NTOK x 229] @ [229 x 648]
// ---------------------------------------------------------------------------
#define K1_TT 16
__global__ void __launch_bounds__(672) k1_proj(
    const float* __restrict__ spec,
    const float* __restrict__ Wf,  const float* __restrict__ bf,
    const float* __restrict__ Wao, const float* __restrict__ bao,
    const float* __restrict__ Wac,
    const float* __restrict__ Wl1,
    const float* __restrict__ Wlc,
    float* __restrict__ out)
{
    __shared__ __align__(16) float sh[NBINS][20];
    const int tok0 = blockIdx.x * K1_TT;

    for (int idx = threadIdx.x; idx < NBINS * K1_TT; idx += 672) {
        int tt = idx / NBINS;
        int k  = idx - tt * NBINS;
        sh[k][tt] = spec[(size_t)(tok0 + tt) * NBINS + k];
    }
    __syncthreads();

    const int j = threadIdx.x;
    if (j >= 648) return;

    const float* wp;
    int stride;
    if (j < 88)       { wp = Wf + j;                          stride = OUTF;  }
    else if (j < 216) { wp = Wao + (j - 88);                  stride = MODEL; }
    else if (j < 344) { wp = Wao + NBINS*MODEL + (j - 216);   stride = MODEL; }
    else if (j < 472) { wp = Wac + 176*MODEL  + (j - 344);    stride = MODEL; }
    else if (j < 560) { wp = Wl1 + (j - 472);                 stride = OUTF;  }
    else              { wp = Wlc + 176*OUTF   + (j - 560);    stride = OUTF;  }

    unsigned long long acc[8];
    #pragma unroll
    for (int p = 0; p < 8; p++) acc[p] = 0ull;

    #pragma unroll 4
    for (int k = 0; k < NBINS; k++) {
        float w = *wp; wp += stride;
        unsigned long long ww = pkf2(w, w);
        const unsigned long long* row = (const unsigned long long*)&sh[k][0];
        #pragma unroll
        for (int p = 0; p < 8; p++) fma2(acc[p], row[p], ww);
    }

    float rv[16];
    #pragma unroll
    for (int p = 0; p < 8; p++) {
        float2 r = upk(acc[p]);
        rv[2*p] = r.x; rv[2*p+1] = r.y;
    }

    const int b    = tok0 >> 10;
    const size_t row0 = (size_t)b * TPAD + WSZ + (tok0 & (TSEQ - 1));

    if (j < 88) {
        float bias = bf[j];
        #pragma unroll
        for (int tt = 0; tt < K1_TT; tt++)
            out[FEAT_OFF + (size_t)(tok0 + tt) * OUTF + j] = rv[tt] + bias;
    } else if (j < 216) {
        int m = j - 88;
        float bias = bao[m];
        #pragma unroll
        for (int tt = 0; tt < K1_TT; tt++)
            g_go[(size_t)(tok0 + tt) * MODEL + m] = rv[tt] + bias;
    } else if (j < 344) {
        int m = j - 216;
        #pragma unroll
        for (int tt = 0; tt < K1_TT; tt++)
            g_uo[(row0 + tt) * MODEL + m] = rv[tt];
    } else if (j < 472) {
        int m = j - 344;
        #pragma unroll
        for (int tt = 0; tt < K1_TT; tt++)
            g_uc[(row0 + tt) * MODEL + m] = rv[tt];
    } else if (j < 560) {
        int m = j - 472;
        #pragma unroll
        for (int tt = 0; tt < K1_TT; tt++)
            g_p12[(row0 + tt) * PCOLS + m] = rv[tt];
    } else {
        int m = j - 560 + 88;
        #pragma unroll
        for (int tt = 0; tt < K1_TT; tt++)
            g_p12[(row0 + tt) * PCOLS + m] = rv[tt];
    }
}

// ---------------------------------------------------------------------------
// k_attn_fused: scores + softmax + windowed P-sum + sigmoid output.
// ---------------------------------------------------------------------------
template<bool PER_TOKEN_ADD>
__global__ void __launch_bounds__(256) k_attn_fused(
    const float* __restrict__ gv,     // [NTOK][128]
    const float* __restrict__ u_pad,  // [4][TPAD][128] guarded
    const float* __restrict__ vvec,   // [128]
    const float* __restrict__ addv,
    const float* __restrict__ ppad,   // g_p12
    int pcol,
    float* __restrict__ a_out,        // [NTOK][61]
    float* __restrict__ p_out)        // [NTOK][88]
{
    const int tok  = blockIdx.x;
    const int b    = tok >> 10;
    const int t    = tok & (TSEQ - 1);
    const int tid  = threadIdx.x;
    const int warp = tid >> 5;
    const int lane = tid & 31;

    __shared__ float sc[64];
    __shared__ float aw[64];
    __shared__ __align__(16) float psum[8][22][4];

    const float4 g4 = *(const float4*)(gv   + (size_t)tok * MODEL + lane * 4);
    const float4 v4 = *(const float4*)(vvec + lane * 4);
    const float4* ubase = (const float4*)(u_pad + (size_t)(b * TPAD + t) * MODEL) + lane;

    #pragma unroll 2
    for (int w = warp; w < WIN; w += 8) {
        float4 u4 = ubase[(size_t)w * 32];
        float p = v4.x * tanh_fast(g4.x + u4.x)
                + v4.y * tanh_fast(g4.y + u4.y)
                + v4.z * tanh_fast(g4.z + u4.z)
                + v4.w * tanh_fast(g4.w + u4.w);
        p = warp_sum(p);
        if (lane == 0) sc[w] = p;
    }
    __syncthreads();

    if (warp == 0) {
        float s0 = (lane < WIN) ? sc[lane] : -1e30f;
        float s1 = (lane + 32 < WIN) ? sc[lane + 32] : -1e30f;
        float mx = warp_max(fmaxf(s0, s1));
        float e0 = (lane < WIN) ? __expf(s0 - mx) : 0.f;
        float e1 = (lane + 32 < WIN) ? __expf(s1 - mx) : 0.f;
        float inv = 1.f / warp_sum(e0 + e1);
        if (lane < WIN) {
            float a = e0 * inv;
            aw[lane] = a;
            a_out[(size_t)tok * WIN + lane] = a;
        }
        if (lane + 32 < WIN) {
            float a = e1 * inv;
            aw[lane + 32] = a;
            a_out[(size_t)tok * WIN + lane + 32] = a;
        }
    }
    __syncthreads();

    // windowed P-sum: 176 threads, (c4 = float4 col 0..21, h = window-slice 0..7)
    if (tid < 176) {
        const int c4 = tid % 22;
        const int h  = tid / 22;
        const float4* pr = (const float4*)(ppad + (size_t)(b * TPAD + t) * PCOLS + pcol) + c4;
        float4 acc = make_float4(0.f, 0.f, 0.f, 0.f);
        #pragma unroll
        for (int w = h; w < WIN; w += 8) {
            float a = aw[w];
            float4 p = pr[(size_t)w * 44];
            acc.x += a * p.x; acc.y += a * p.y; acc.z += a * p.z; acc.w += a * p.w;
        }
        *(float4*)&psum[h][c4][0] = acc;
    }
    __syncthreads();

    if (tid < OUTF) {
        const int c4 = tid >> 2, cm = tid & 3;
        float acc = psum[0][c4][cm] + psum[1][c4][cm] + psum[2][c4][cm] + psum[3][c4][cm]
                  + psum[4][c4][cm] + psum[5][c4][cm] + psum[6][c4][cm] + psum[7][c4][cm];
        float addt = PER_TOKEN_ADD ? addv[(size_t)tok * OUTF + tid] : addv[tid];
        p_out[(size_t)tok * OUTF + tid] = sigmoid_fast(acc + addt);
    }
}

// ---------------------------------------------------------------------------
// k2b: 8 tokens/block, 2-way K-split, 448 threads (432 active).
//   g_c = x @ Wac_top + bac   (cols 0..127)
//   xl  = x @ Wlc_top + blc   (cols 128..215)
// ---------------------------------------------------------------------------
#define K2_TT 8
__global__ void __launch_bounds__(448) k2b_gc_xl(
    const float* __restrict__ Wac, const float* __restrict__ bac,
    const float* __restrict__ Wlc, const float* __restrict__ blc,
    const float* __restrict__ out)
{
    __shared__ __align__(16) float A[176][K2_TT];
    __shared__ float part[216][K2_TT];
    const int tok0 = blockIdx.x * K2_TT;
    const int tid = threadIdx.x;

    for (int idx = tid; idx < 176 * K2_TT; idx += 448) {
        int tt = idx / 176, r = idx - tt * 176;
        float v = (r < 88)
            ? out[FEAT_OFF  + (size_t)(tok0 + tt) * OUTF + r]
            : out[ONSET_OFF + (size_t)(tok0 + tt) * OUTF + (r - 88)];
        A[r][tt] = v;
    }
    __syncthreads();

    const int s = (tid >= 216);            // k-split half
    const int j = tid - s * 216;           // output column 0..215
    const bool active = (tid < 432);

    float rv[K2_TT];
    if (active) {
        const float* wp;
        int stride;
        if (j < 128) { wp = Wac + j;         stride = MODEL; }
        else         { wp = Wlc + (j - 128); stride = OUTF;  }
        wp += (size_t)(s * 88) * stride;

        unsigned long long acc[K2_TT / 2];
        #pragma unroll
        for (int p = 0; p < K2_TT / 2; p++) acc[p] = 0ull;

        const int k0 = s * 88;
        #pragma unroll 4
        for (int k = k0; k < k0 + 88; k++) {
            float w = *wp; wp += stride;
            unsigned long long ww = pkf2(w, w);
            const unsigned long long* row = (const unsigned long long*)&A[k][0];
            #pragma unroll
            for (int p = 0; p < K2_TT / 2; p++) fma2(acc[p], row[p], ww);
        }
        #pragma unroll
        for (int p = 0; p < K2_TT / 2; p++) {
            float2 r = upk(acc[p]);
            rv[2*p] = r.x; rv[2*p+1] = r.y;
        }
        if (s == 1) {
            #pragma unroll
            for (int tt = 0; tt < K2_TT; tt++) part[j][tt] = rv[tt];
        }
    }
    __syncthreads();

    if (active && s == 0) {
        if (j < 128) {
            float bias = bac[j];
            #pragma unroll
            for (int tt = 0; tt < K2_TT; tt++)
                g_gc[(size_t)(tok0 + tt) * MODEL + j] = rv[tt] + part[j][tt] + bias;
        } else {
            int m = j - 128;
            float bias = blc[m];
            #pragma unroll
            for (int tt = 0; tt < K2_TT; tt++)
                g_xl[(size_t)(tok0 + tt) * OUTF + m] = rv[tt] + part[j][tt] + bias;
        }
    }
}

extern "C" void kernel_launch(void* const* d_in, const int* in_sizes, int n_in,
                              void* d_out, int out_size)
{
    const float* spec = (const float*)d_in[0];
    const float* Wf   = (const float*)d_in[1];
    const float* bf   = (const float*)d_in[2];
    const float* Wao  = (const float*)d_in[3];
    const float* bao  = (const float*)d_in[4];
    const float* vo   = (const float*)d_in[5];
    const float* Wl1  = (const float*)d_in[6];
    const float* bl1  = (const float*)d_in[7];
    const float* Wac  = (const float*)d_in[8];
    const float* bac  = (const float*)d_in[9];
    const float* vc   = (const float*)d_in[10];
    const float* Wlc  = (const float*)d_in[11];
    const float* blc  = (const float*)d_in[12];
    float* out = (float*)d_out;

    float *p_go, *p_uo, *p_uc, *p_gc, *p_p12, *p_xl;
    cudaGetSymbolAddress((void**)&p_go,  g_go);
    cudaGetSymbolAddress((void**)&p_uo,  g_uo);
    cudaGetSymbolAddress((void**)&p_uc,  g_uc);
    cudaGetSymbolAddress((void**)&p_gc,  g_gc);
    cudaGetSymbolAddress((void**)&p_p12, g_p12);
    cudaGetSymbolAddress((void**)&p_xl,  g_xl);

    k1_proj<<<NTOK / K1_TT, 672>>>(spec, Wf, bf, Wao, bao, Wac, Wl1, Wlc, out);
    k_attn_fused<false><<<NTOK, 256>>>(p_go, p_uo, vo, bl1, p_p12, 0,
                                       out + AONSET_OFF, out + ONSET_OFF);
    k2b_gc_xl<<<NTOK / K2_TT, 448>>>(Wac, bac, Wlc, blc, out);
    k_attn_fused<true><<<NTOK, 256>>>(p_gc, p_uc, vc, p_xl, p_p12, 88,
                                      out + AFRAME_OFF, out + FRAME_OFF);
}

// round 6
// speedup vs baseline: 2.7652x; 1.0930x over previous
#include <cuda_runtime.h>
#include <math.h>

#define NBINS 229
#define OUTF  88
#define MODEL 128
#define WSZ   30
#define WIN   61
#define TSEQ  1024
#define NTOK  4096
#define TPAD  1084            // 30 + 1024 + 30
#define PCOLS 176             // P1(88) | P2(88)
#define AT_TT 16              // tokens per attention block
#define AT_ROWS (AT_TT + 2*WSZ)   // 76 staged window rows

// Output layout (floats): frame_pred, a_frame, onset_pred, a_onset, feat_pred
#define FRAME_OFF  0
#define AFRAME_OFF (NTOK*OUTF)
#define ONSET_OFF  (AFRAME_OFF + NTOK*WIN)
#define AONSET_OFF (ONSET_OFF + NTOK*OUTF)
#define FEAT_OFF   (AONSET_OFF + NTOK*WIN)

// Scratch (__device__ globals; zero-initialized at module load — guard rows
// of g_uo/g_uc/g_p12 are never written, so they stay zero forever).
__device__ float g_go[NTOK * MODEL];
__device__ float g_uo[4 * TPAD * MODEL];
__device__ float g_uc[4 * TPAD * MODEL];
__device__ float g_p12[4 * TPAD * PCOLS];
__device__ float g_gc[NTOK * MODEL];
__device__ float g_xl[NTOK * OUTF];

__device__ __forceinline__ float tanh_fast(float x) {
    float y; asm("tanh.approx.f32 %0, %1;" : "=f"(y) : "f"(x)); return y;
}
__device__ __forceinline__ float sigmoid_fast(float x) {
    return 1.f / (1.f + __expf(-x));
}
__device__ __forceinline__ unsigned long long pkf2(float lo, float hi) {
    unsigned long long r;
    asm("mov.b64 %0, {%1, %2};" : "=l"(r) : "f"(lo), "f"(hi));
    return r;
}
__device__ __forceinline__ void fma2(unsigned long long& acc,
                                     unsigned long long a, unsigned long long b) {
    asm("fma.rn.f32x2 %0, %1, %2, %0;" : "+l"(acc) : "l"(a), "l"(b));
}
__device__ __forceinline__ float2 upk(unsigned long long v) {
    float2 r;
    asm("mov.b64 {%0, %1}, %2;" : "=f"(r.x), "=f"(r.y) : "l"(v));
    return r;
}
__device__ __forceinline__ float warp_sum(float v) {
    v += __shfl_xor_sync(0xFFFFFFFFu, v, 16);
    v += __shfl_xor_sync(0xFFFFFFFFu, v, 8);
    v += __shfl_xor_sync(0xFFFFFFFFu, v, 4);
    v += __shfl_xor_sync(0xFFFFFFFFu, v, 2);
    v += __shfl_xor_sync(0xFFFFFFFFu, v, 1);
    return v;
}
__device__ __forceinline__ float warp_max(float v) {
    v = fmaxf(v, __shfl_xor_sync(0xFFFFFFFFu, v, 16));
    v = fmaxf(v, __shfl_xor_sync(0xFFFFFFFFu, v, 8));
    v = fmaxf(v, __shfl_xor_sync(0xFFFFFFFFu, v, 4));
    v = fmaxf(v, __shfl_xor_sync(0xFFFFFFFFu, v, 2));
    v = fmaxf(v, __shfl_xor_sync(0xFFFFFFFFu, v, 1));
    return v;
}

// ---------------------------------------------------------------------------
// k1: mega projection GEMM  [NTOK x 229] @ [229 x 648], 2 cols per thread
// ---------------------------------------------------------------------------
#define K1_TT 16
__device__ __forceinline__ const float* k1_col_ptr(
    int j, int& stride,
    const float* Wf, const float* Wao, const float* Wac,
    const float* Wl1, const float* Wlc)
{
    if (j < 88)       { stride = OUTF;  return Wf + j; }
    else if (j < 216) { stride = MODEL; return Wao + (j - 88); }
    else if (j < 344) { stride = MODEL; return Wao + NBINS*MODEL + (j - 216); }
    else if (j < 472) { stride = MODEL; return Wac + 176*MODEL  + (j - 344); }
    else if (j < 560) { stride = OUTF;  return Wl1 + (j - 472); }
    else              { stride = OUTF;  return Wlc + 176*OUTF   + (j - 560); }
}

__device__ __forceinline__ void k1_store(
    int j, const float rv[K1_TT], int tok0, size_t row0,
    const float* bf, const float* bao, float* out)
{
    if (j < 88) {
        float bias = bf[j];
        #pragma unroll
        for (int tt = 0; tt < K1_TT; tt++)
            out[FEAT_OFF + (size_t)(tok0 + tt) * OUTF + j] = rv[tt] + bias;
    } else if (j < 216) {
        int m = j - 88;
        float bias = bao[m];
        #pragma unroll
        for (int tt = 0; tt < K1_TT; tt++)
            g_go[(size_t)(tok0 + tt) * MODEL + m] = rv[tt] + bias;
    } else if (j < 344) {
        int m = j - 216;
        #pragma unroll
        for (int tt = 0; tt < K1_TT; tt++)
            g_uo[(row0 + tt) * MODEL + m] = rv[tt];
    } else if (j < 472) {
        int m = j - 344;
        #pragma unroll
        for (int tt = 0; tt < K1_TT; tt++)
            g_uc[(row0 + tt) * MODEL + m] = rv[tt];
    } else if (j < 560) {
        int m = j - 472;
        #pragma unroll
        for (int tt = 0; tt < K1_TT; tt++)
            g_p12[(row0 + tt) * PCOLS + m] = rv[tt];
    } else {
        int m = j - 560 + 88;
        #pragma unroll
        for (int tt = 0; tt < K1_TT; tt++)
            g_p12[(row0 + tt) * PCOLS + m] = rv[tt];
    }
}

__global__ void __launch_bounds__(384) k1_proj(
    const float* __restrict__ spec,
    const float* __restrict__ Wf,  const float* __restrict__ bf,
    const float* __restrict__ Wao, const float* __restrict__ bao,
    const float* __restrict__ Wac,
    const float* __restrict__ Wl1,
    const float* __restrict__ Wlc,
    float* __restrict__ out)
{
    __shared__ __align__(16) float sh[NBINS][20];
    const int tok0 = blockIdx.x * K1_TT;

    for (int idx = threadIdx.x; idx < NBINS * K1_TT; idx += 384) {
        int tt = idx / NBINS;
        int k  = idx - tt * NBINS;
        sh[k][tt] = spec[(size_t)(tok0 + tt) * NBINS + k];
    }
    __syncthreads();

    const int j0 = threadIdx.x;
    if (j0 >= 324) return;
    const int j1 = j0 + 324;

    int st0, st1;
    const float* wp0 = k1_col_ptr(j0, st0, Wf, Wao, Wac, Wl1, Wlc);
    const float* wp1 = k1_col_ptr(j1, st1, Wf, Wao, Wac, Wl1, Wlc);

    unsigned long long acc0[8], acc1[8];
    #pragma unroll
    for (int p = 0; p < 8; p++) { acc0[p] = 0ull; acc1[p] = 0ull; }

    #pragma unroll 2
    for (int k = 0; k < NBINS; k++) {
        float w0 = *wp0; wp0 += st0;
        float w1 = *wp1; wp1 += st1;
        unsigned long long ww0 = pkf2(w0, w0);
        unsigned long long ww1 = pkf2(w1, w1);
        const unsigned long long* row = (const unsigned long long*)&sh[k][0];
        unsigned long long r[8];
        #pragma unroll
        for (int p = 0; p < 8; p++) r[p] = row[p];
        #pragma unroll
        for (int p = 0; p < 8; p++) fma2(acc0[p], r[p], ww0);
        #pragma unroll
        for (int p = 0; p < 8; p++) fma2(acc1[p], r[p], ww1);
    }

    const size_t row0 = (size_t)(tok0 >> 10) * TPAD + WSZ + (tok0 & (TSEQ - 1));
    float rv[K1_TT];
    #pragma unroll
    for (int p = 0; p < 8; p++) {
        float2 r = upk(acc0[p]);
        rv[2*p] = r.x; rv[2*p+1] = r.y;
    }
    k1_store(j0, rv, tok0, row0, bf, bao, out);
    #pragma unroll
    for (int p = 0; p < 8; p++) {
        float2 r = upk(acc1[p]);
        rv[2*p] = r.x; rv[2*p+1] = r.y;
    }
    k1_store(j1, rv, tok0, row0, bf, bao, out);
}

// ---------------------------------------------------------------------------
// k_attn_tiled: 16 tokens/block, 512 threads (warp == token).
// Stages u[76][128] + p[76][88] in dynamic smem; after one __syncthreads,
// each warp runs scores -> softmax -> windowed P-sum -> sigmoid independently.
// ---------------------------------------------------------------------------
template<bool PER_TOKEN_ADD>
__global__ void __launch_bounds__(512) k_attn_tiled(
    const float* __restrict__ gv,     // [NTOK][128]
    const float* __restrict__ u_pad,  // [4][TPAD][128] guarded
    const float* __restrict__ vvec,   // [128]
    const float* __restrict__ addv,
    const float* __restrict__ ppad,   // g_p12
    int pcol,
    float* __restrict__ a_out,        // [NTOK][61]
    float* __restrict__ p_out)        // [NTOK][88]
{
    extern __shared__ __align__(16) float smem[];
    float* u_tile = smem;                         // [76][128]
    float* p_tile = smem + AT_ROWS * MODEL;       // [76][88]
    float* sc     = p_tile + AT_ROWS * OUTF;      // [16][64]

    const int tok0 = blockIdx.x * AT_TT;
    const int b    = tok0 >> 10;
    const int t0   = tok0 & (TSEQ - 1);
    const int tid  = threadIdx.x;
    const int warp = tid >> 5;
    const int lane = tid & 31;

    // ---- stage u tile: 76 rows x 32 float4 (contiguous in global) ----
    {
        const float4* usrc = (const float4*)(u_pad + ((size_t)b * TPAD + t0) * MODEL);
        float4* udst = (float4*)u_tile;
        #pragma unroll
        for (int i = tid; i < AT_ROWS * 32; i += 512) udst[i] = usrc[i];
    }
    // ---- stage p tile: 76 rows x 22 float4 (global row stride 44) ----
    {
        const float4* psrc = (const float4*)(ppad + ((size_t)b * TPAD + t0) * PCOLS + pcol);
        float4* pdst = (float4*)p_tile;
        #pragma unroll
        for (int i = tid; i < AT_ROWS * 22; i += 512) {
            int r = i / 22, c = i - r * 22;
            pdst[i] = psrc[(size_t)r * 44 + c];
        }
    }
    __syncthreads();

    const int tok = tok0 + warp;
    const float4 g4 = ((const float4*)(gv + (size_t)tok * MODEL))[lane];
    const float4 v4 = ((const float4*)vvec)[lane];
    float* scrow = sc + warp * 64;

    // ---- scores: warp's token, 61 windows from shared ----
    const float4* ub = (const float4*)u_tile + (size_t)warp * 32 + lane;
    for (int w = 0; w < WIN; w++) {
        float4 u4 = ub[(size_t)w * 32];
        float p = v4.x * tanh_fast(g4.x + u4.x)
                + v4.y * tanh_fast(g4.y + u4.y)
                + v4.z * tanh_fast(g4.z + u4.z)
                + v4.w * tanh_fast(g4.w + u4.w);
        p = warp_sum(p);
        if (lane == 0) scrow[w] = p;
    }
    __syncwarp();

    // ---- softmax (per-warp) ----
    float s0 = (lane < WIN) ? scrow[lane] : -1e30f;
    float s1 = (lane + 32 < WIN) ? scrow[lane + 32] : -1e30f;
    float mx = warp_max(fmaxf(s0, s1));
    float e0 = (lane < WIN) ? __expf(s0 - mx) : 0.f;
    float e1 = (lane + 32 < WIN) ? __expf(s1 - mx) : 0.f;
    float inv = 1.f / warp_sum(e0 + e1);
    float a0 = e0 * inv, a1 = e1 * inv;
    __syncwarp();
    if (lane < WIN) {
        scrow[lane] = a0;
        a_out[(size_t)tok * WIN + lane] = a0;
    }
    if (lane + 32 < WIN) {
        scrow[lane + 32] = a1;
        a_out[(size_t)tok * WIN + lane + 32] = a1;
    }
    __syncwarp();

    // ---- windowed P-sum: 88 cols, lanes handle c, c+32, c+64 ----
    float acc0 = 0.f, acc1 = 0.f, acc2 = 0.f;
    const float* pb = p_tile + (size_t)warp * OUTF;
    #pragma unroll 4
    for (int w = 0; w < WIN; w++) {
        float a = scrow[w];
        const float* pr = pb + (size_t)w * OUTF;
        acc0 += a * pr[lane];
        acc1 += a * pr[lane + 32];
        if (lane < 24) acc2 += a * pr[lane + 64];
    }
    {
        float ad0 = PER_TOKEN_ADD ? addv[(size_t)tok * OUTF + lane]      : addv[lane];
        float ad1 = PER_TOKEN_ADD ? addv[(size_t)tok * OUTF + lane + 32] : addv[lane + 32];
        p_out[(size_t)tok * OUTF + lane]      = sigmoid_fast(acc0 + ad0);
        p_out[(size_t)tok * OUTF + lane + 32] = sigmoid_fast(acc1 + ad1);
        if (lane < 24) {
            float ad2 = PER_TOKEN_ADD ? addv[(size_t)tok * OUTF + lane + 64] : addv[lane + 64];
            p_out[(size_t)tok * OUTF + lane + 64] = sigmoid_fast(acc2 + ad2);
        }
    }
}

// ---------------------------------------------------------------------------
// k2b: 8 tokens/block, 2-way K-split, 448 threads (432 active).
// ---------------------------------------------------------------------------
#define K2_TT 8
__global__ void __launch_bounds__(448) k2b_gc_xl(
    const float* __restrict__ Wac, const float* __restrict__ bac,
    const float* __restrict__ Wlc, const float* __restrict__ blc,
    const float* __restrict__ out)
{
    __shared__ __align__(16) float A[176][K2_TT];
    __shared__ float part[216][K2_TT];
    const int tok0 = blockIdx.x * K2_TT;
    const int tid = threadIdx.x;

    for (int idx = tid; idx < 176 * K2_TT; idx += 448) {
        int tt = idx / 176, r = idx - tt * 176;
        float v = (r < 88)
            ? out[FEAT_OFF  + (size_t)(tok0 + tt) * OUTF + r]
            : out[ONSET_OFF + (size_t)(tok0 + tt) * OUTF + (r - 88)];
        A[r][tt] = v;
    }
    __syncthreads();

    const int s = (tid >= 216);
    const int j = tid - s * 216;
    const bool active = (tid < 432);

    float rv[K2_TT];
    if (active) {
        const float* wp;
        int stride;
        if (j < 128) { wp = Wac + j;         stride = MODEL; }
        else         { wp = Wlc + (j - 128); stride = OUTF;  }
        wp += (size_t)(s * 88) * stride;

        unsigned long long acc[K2_TT / 2];
        #pragma unroll
        for (int p = 0; p < K2_TT / 2; p++) acc[p] = 0ull;

        const int k0 = s * 88;
        #pragma unroll 4
        for (int k = k0; k < k0 + 88; k++) {
            float w = *wp; wp += stride;
            unsigned long long ww = pkf2(w, w);
            const unsigned long long* row = (const unsigned long long*)&A[k][0];
            #pragma unroll
            for (int p = 0; p < K2_TT / 2; p++) fma2(acc[p], row[p], ww);
        }
        #pragma unroll
        for (int p = 0; p < K2_TT / 2; p++) {
            float2 r = upk(acc[p]);
            rv[2*p] = r.x; rv[2*p+1] = r.y;
        }
        if (s == 1) {
            #pragma unroll
            for (int tt = 0; tt < K2_TT; tt++) part[j][tt] = rv[tt];
        }
    }
    __syncthreads();

    if (active && s == 0) {
        if (j < 128) {
            float bias = bac[j];
            #pragma unroll
            for (int tt = 0; tt < K2_TT; tt++)
                g_gc[(size_t)(tok0 + tt) * MODEL + j] = rv[tt] + part[j][tt] + bias;
        } else {
            int m = j - 128;
            float bias = blc[m];
            #pragma unroll
            for (int tt = 0; tt < K2_TT; tt++)
                g_xl[(size_t)(tok0 + tt) * OUTF + m] = rv[tt] + part[j][tt] + bias;
        }
    }
}

extern "C" void kernel_launch(void* const* d_in, const int* in_sizes, int n_in,
                              void* d_out, int out_size)
{
    const float* spec = (const float*)d_in[0];
    const float* Wf   = (const float*)d_in[1];
    const float* bf   = (const float*)d_in[2];
    const float* Wao  = (const float*)d_in[3];
    const float* bao  = (const float*)d_in[4];
    const float* vo   = (const float*)d_in[5];
    const float* Wl1  = (const float*)d_in[6];
    const float* bl1  = (const float*)d_in[7];
    const float* Wac  = (const float*)d_in[8];
    const float* bac  = (const float*)d_in[9];
    const float* vc   = (const float*)d_in[10];
    const float* Wlc  = (const float*)d_in[11];
    const float* blc  = (const float*)d_in[12];
    float* out = (float*)d_out;

    float *p_go, *p_uo, *p_uc, *p_gc, *p_p12, *p_xl;
    cudaGetSymbolAddress((void**)&p_go,  g_go);
    cudaGetSymbolAddress((void**)&p_uo,  g_uo);
    cudaGetSymbolAddress((void**)&p_uc,  g_uc);
    cudaGetSymbolAddress((void**)&p_gc,  g_gc);
    cudaGetSymbolAddress((void**)&p_p12, g_p12);
    cudaGetSymbolAddress((void**)&p_xl,  g_xl);

    const int smem_bytes = (AT_ROWS * MODEL + AT_ROWS * OUTF + AT_TT * 64) * 4; // ~69.8KB
    cudaFuncSetAttribute(k_attn_tiled<false>,
                         cudaFuncAttributeMaxDynamicSharedMemorySize, smem_bytes);
    cudaFuncSetAttribute(k_attn_tiled<true>,
                         cudaFuncAttributeMaxDynamicSharedMemorySize, smem_bytes);

    k1_proj<<<NTOK / K1_TT, 384>>>(spec, Wf, bf, Wao, bao, Wac, Wl1, Wlc, out);
    k_attn_tiled<false><<<NTOK / AT_TT, 512, smem_bytes>>>(
        p_go, p_uo, vo, bl1, p_p12, 0, out + AONSET_OFF, out + ONSET_OFF);
    k2b_gc_xl<<<NTOK / K2_TT, 448>>>(Wac, bac, Wlc, blc, out);
    k_attn_tiled<true><<<NTOK / AT_TT, 512, smem_bytes>>>(
        p_gc, p_uc, vc, p_xl, p_p12, 88, out + AFRAME_OFF, out + FRAME_OFF);
}

// round 7
// speedup vs baseline: 2.9128x; 1.0534x over previous
#include <cuda_runtime.h>
#include <math.h>

#define NBINS 229
#define OUTF  88
#define MODEL 128
#define WSZ   30
#define WIN   61
#define TSEQ  1024
#define NTOK  4096
#define TPAD  1084            // 30 + 1024 + 30
#define PCOLS 176             // P1(88) | P2(88)
#define AT_TT 16              // tokens per attention block
#define AT_ROWS (AT_TT + 2*WSZ)   // 76 staged window rows
#define UPITCH 132            // padded u row (33 float4) -> conflict-free
#define UP4 (UPITCH/4)

// Output layout (floats): frame_pred, a_frame, onset_pred, a_onset, feat_pred
#define FRAME_OFF  0
#define AFRAME_OFF (NTOK*OUTF)
#define ONSET_OFF  (AFRAME_OFF + NTOK*WIN)
#define AONSET_OFF (ONSET_OFF + NTOK*OUTF)
#define FEAT_OFF   (AONSET_OFF + NTOK*WIN)

// Scratch (__device__ globals; zero-initialized at load — guard rows of
// g_uo/g_uc/g_p12 are never written, so they stay zero forever).
__device__ float g_go[NTOK * MODEL];
__device__ float g_uo[4 * TPAD * MODEL];
__device__ float g_uc[4 * TPAD * MODEL];
__device__ float g_p12[4 * TPAD * PCOLS];
__device__ float g_gc[NTOK * MODEL];
__device__ float g_xl[NTOK * OUTF];

__device__ __forceinline__ float tanh_fast(float x) {
    float y; asm("tanh.approx.f32 %0, %1;" : "=f"(y) : "f"(x)); return y;
}
__device__ __forceinline__ float sigmoid_fast(float x) {
    return 1.f / (1.f + __expf(-x));
}
__device__ __forceinline__ unsigned long long pkf2(float lo, float hi) {
    unsigned long long r;
    asm("mov.b64 %0, {%1, %2};" : "=l"(r) : "f"(lo), "f"(hi));
    return r;
}
__device__ __forceinline__ void fma2(unsigned long long& acc,
                                     unsigned long long a, unsigned long long b) {
    asm("fma.rn.f32x2 %0, %1, %2, %0;" : "+l"(acc) : "l"(a), "l"(b));
}
__device__ __forceinline__ float2 upk(unsigned long long v) {
    float2 r;
    asm("mov.b64 {%0, %1}, %2;" : "=f"(r.x), "=f"(r.y) : "l"(v));
    return r;
}
__device__ __forceinline__ float warp_sum(float v) {
    v += __shfl_xor_sync(0xFFFFFFFFu, v, 16);
    v += __shfl_xor_sync(0xFFFFFFFFu, v, 8);
    v += __shfl_xor_sync(0xFFFFFFFFu, v, 4);
    v += __shfl_xor_sync(0xFFFFFFFFu, v, 2);
    v += __shfl_xor_sync(0xFFFFFFFFu, v, 1);
    return v;
}
__device__ __forceinline__ float warp_max(float v) {
    v = fmaxf(v, __shfl_xor_sync(0xFFFFFFFFu, v, 16));
    v = fmaxf(v, __shfl_xor_sync(0xFFFFFFFFu, v, 8));
    v = fmaxf(v, __shfl_xor_sync(0xFFFFFFFFu, v, 4));
    v = fmaxf(v, __shfl_xor_sync(0xFFFFFFFFu, v, 2));
    v = fmaxf(v, __shfl_xor_sync(0xFFFFFFFFu, v, 1));
    return v;
}

// ---------------------------------------------------------------------------
// k1: mega projection GEMM  [NTOK x 229] @ [229 x 648], 2 cols per thread
// ---------------------------------------------------------------------------
#define K1_TT 16
__device__ __forceinline__ const float* k1_col_ptr(
    int j, int& stride,
    const float* Wf, const float* Wao, const float* Wac,
    const float* Wl1, const float* Wlc)
{
    if (j < 88)       { stride = OUTF;  return Wf + j; }
    else if (j < 216) { stride = MODEL; return Wao + (j - 88); }
    else if (j < 344) { stride = MODEL; return Wao + NBINS*MODEL + (j - 216); }
    else if (j < 472) { stride = MODEL; return Wac + 176*MODEL  + (j - 344); }
    else if (j < 560) { stride = OUTF;  return Wl1 + (j - 472); }
    else              { stride = OUTF;  return Wlc + 176*OUTF   + (j - 560); }
}

__device__ __forceinline__ void k1_store(
    int j, const float rv[K1_TT], int tok0, size_t row0,
    const float* bf, const float* bao, float* out)
{
    if (j < 88) {
        float bias = bf[j];
        #pragma unroll
        for (int tt = 0; tt < K1_TT; tt++)
            out[FEAT_OFF + (size_t)(tok0 + tt) * OUTF + j] = rv[tt] + bias;
    } else if (j < 216) {
        int m = j - 88;
        float bias = bao[m];
        #pragma unroll
        for (int tt = 0; tt < K1_TT; tt++)
            g_go[(size_t)(tok0 + tt) * MODEL + m] = rv[tt] + bias;
    } else if (j < 344) {
        int m = j - 216;
        #pragma unroll
        for (int tt = 0; tt < K1_TT; tt++)
            g_uo[(row0 + tt) * MODEL + m] = rv[tt];
    } else if (j < 472) {
        int m = j - 344;
        #pragma unroll
        for (int tt = 0; tt < K1_TT; tt++)
            g_uc[(row0 + tt) * MODEL + m] = rv[tt];
    } else if (j < 560) {
        int m = j - 472;
        #pragma unroll
        for (int tt = 0; tt < K1_TT; tt++)
            g_p12[(row0 + tt) * PCOLS + m] = rv[tt];
    } else {
        int m = j - 560 + 88;
        #pragma unroll
        for (int tt = 0; tt < K1_TT; tt++)
            g_p12[(row0 + tt) * PCOLS + m] = rv[tt];
    }
}

__global__ void __launch_bounds__(384) k1_proj(
    const float* __restrict__ spec,
    const float* __restrict__ Wf,  const float* __restrict__ bf,
    const float* __restrict__ Wao, const float* __restrict__ bao,
    const float* __restrict__ Wac,
    const float* __restrict__ Wl1,
    const float* __restrict__ Wlc,
    float* __restrict__ out)
{
    __shared__ __align__(16) float sh[NBINS][20];
    const int tok0 = blockIdx.x * K1_TT;

    for (int idx = threadIdx.x; idx < NBINS * K1_TT; idx += 384) {
        int tt = idx / NBINS;
        int k  = idx - tt * NBINS;
        sh[k][tt] = spec[(size_t)(tok0 + tt) * NBINS + k];
    }
    __syncthreads();

    const int j0 = threadIdx.x;
    if (j0 >= 324) return;
    const int j1 = j0 + 324;

    int st0, st1;
    const float* wp0 = k1_col_ptr(j0, st0, Wf, Wao, Wac, Wl1, Wlc);
    const float* wp1 = k1_col_ptr(j1, st1, Wf, Wao, Wac, Wl1, Wlc);

    unsigned long long acc0[8], acc1[8];
    #pragma unroll
    for (int p = 0; p < 8; p++) { acc0[p] = 0ull; acc1[p] = 0ull; }

    #pragma unroll 2
    for (int k = 0; k < NBINS; k++) {
        float w0 = *wp0; wp0 += st0;
        float w1 = *wp1; wp1 += st1;
        unsigned long long ww0 = pkf2(w0, w0);
        unsigned long long ww1 = pkf2(w1, w1);
        const unsigned long long* row = (const unsigned long long*)&sh[k][0];
        unsigned long long r[8];
        #pragma unroll
        for (int p = 0; p < 8; p++) r[p] = row[p];
        #pragma unroll
        for (int p = 0; p < 8; p++) fma2(acc0[p], r[p], ww0);
        #pragma unroll
        for (int p = 0; p < 8; p++) fma2(acc1[p], r[p], ww1);
    }

    const size_t row0 = (size_t)(tok0 >> 10) * TPAD + WSZ + (tok0 & (TSEQ - 1));
    float rv[K1_TT];
    #pragma unroll
    for (int p = 0; p < 8; p++) {
        float2 r = upk(acc0[p]);
        rv[2*p] = r.x; rv[2*p+1] = r.y;
    }
    k1_store(j0, rv, tok0, row0, bf, bao, out);
    #pragma unroll
    for (int p = 0; p < 8; p++) {
        float2 r = upk(acc1[p]);
        rv[2*p] = r.x; rv[2*p+1] = r.y;
    }
    k1_store(j1, rv, tok0, row0, bf, bao, out);
}

// ---------------------------------------------------------------------------
// k_attn_tiled: 16 tokens/block (warp == token), 512 threads.
// Score loop: each LANE owns whole windows (lane, lane+32) -> no shuffles.
// u tile padded to 132 floats/row (conflict-free LDS.128 across rows).
// ---------------------------------------------------------------------------
template<bool PER_TOKEN_ADD>
__global__ void __launch_bounds__(512) k_attn_tiled(
    const float* __restrict__ gv,     // [NTOK][128]
    const float* __restrict__ u_pad,  // [4][TPAD][128] guarded
    const float* __restrict__ vvec,   // [128]
    const float* __restrict__ addv,
    const float* __restrict__ ppad,   // g_p12
    int pcol,
    float* __restrict__ a_out,        // [NTOK][61]
    float* __restrict__ p_out)        // [NTOK][88]
{
    extern __shared__ __align__(16) float smem[];
    float* u_tile = smem;                                  // [76][132]
    float* p_tile = u_tile + AT_ROWS * UPITCH;             // [76][88]
    float* s_g    = p_tile + AT_ROWS * OUTF;               // [16][128]
    float* s_v    = s_g + AT_TT * MODEL;                   // [128]
    float* sc     = s_v + MODEL;                           // [16][64]

    const int tok0 = blockIdx.x * AT_TT;
    const int b    = tok0 >> 10;
    const int t0   = tok0 & (TSEQ - 1);
    const int tid  = threadIdx.x;
    const int warp = tid >> 5;
    const int lane = tid & 31;

    // ---- stage u tile (row pitch 33 float4) ----
    {
        const float4* usrc = (const float4*)(u_pad + ((size_t)b * TPAD + t0) * MODEL);
        float4* udst = (float4*)u_tile;
        #pragma unroll
        for (int i = tid; i < AT_ROWS * 32; i += 512) {
            int r = i >> 5, c = i & 31;
            udst[r * UP4 + c] = usrc[i];
        }
    }
    // ---- stage p tile (22 float4/row) ----
    {
        const float4* psrc = (const float4*)(ppad + ((size_t)b * TPAD + t0) * PCOLS + pcol);
        float4* pdst = (float4*)p_tile;
        #pragma unroll
        for (int i = tid; i < AT_ROWS * 22; i += 512) {
            int r = i / 22, c = i - r * 22;
            pdst[i] = psrc[(size_t)r * 44 + c];
        }
    }
    // ---- stage g (16 tokens) and v ----
    {
        const float4* gsrc = (const float4*)(gv + (size_t)tok0 * MODEL);
        float4* gdst = (float4*)s_g;
        #pragma unroll
        for (int i = tid; i < AT_TT * 32; i += 512) gdst[i] = gsrc[i];
        if (tid < 32) ((float4*)s_v)[tid] = ((const float4*)vvec)[tid];
    }
    __syncthreads();

    const int tok = tok0 + warp;
    float* scrow = sc + warp * 64;

    // ---- scores: lane owns windows w1=lane, w2=lane+32 ----
    {
        const int w1 = lane;
        const int w2 = lane + 32;
        const bool has2 = (w2 < WIN);
        const float4* u1 = (const float4*)u_tile + (size_t)(warp + w1) * UP4;
        const float4* u2 = (const float4*)u_tile + (size_t)(warp + (has2 ? w2 : 0)) * UP4;
        const float4* gp = (const float4*)(s_g + warp * MODEL);
        const float4* vp = (const float4*)s_v;

        float a1a = 0.f, a1b = 0.f, a2a = 0.f, a2b = 0.f;
        #pragma unroll 8
        for (int i = 0; i < 32; i++) {
            float4 g4 = gp[i];
            float4 v4 = vp[i];
            float4 x1 = u1[i];
            a1a += v4.x * tanh_fast(g4.x + x1.x) + v4.y * tanh_fast(g4.y + x1.y);
            a1b += v4.z * tanh_fast(g4.z + x1.z) + v4.w * tanh_fast(g4.w + x1.w);
            float4 x2 = u2[i];
            a2a += v4.x * tanh_fast(g4.x + x2.x) + v4.y * tanh_fast(g4.y + x2.y);
            a2b += v4.z * tanh_fast(g4.z + x2.z) + v4.w * tanh_fast(g4.w + x2.w);
        }
        scrow[w1] = a1a + a1b;
        if (has2) scrow[w2] = a2a + a2b;
    }
    __syncwarp();

    // ---- softmax (per-warp) ----
    float s0 = scrow[lane];
    float s1 = (lane + 32 < WIN) ? scrow[lane + 32] : -1e30f;
    float mx = warp_max(fmaxf(s0, s1));
    float e0 = __expf(s0 - mx);
    float e1 = (lane + 32 < WIN) ? __expf(s1 - mx) : 0.f;
    float inv = 1.f / warp_sum(e0 + e1);
    float a0 = e0 * inv, a1 = e1 * inv;
    __syncwarp();
    if (lane < WIN) {
        scrow[lane] = a0;
        a_out[(size_t)tok * WIN + lane] = a0;
    }
    if (lane + 32 < WIN) {
        scrow[lane + 32] = a1;
        a_out[(size_t)tok * WIN + lane + 32] = a1;
    }
    __syncwarp();

    // ---- windowed P-sum: lanes 0..21, one float4 column group each ----
    if (lane < 22) {
        const float4* pb = (const float4*)p_tile + (size_t)warp * 22 + lane;
        float4 acc = make_float4(0.f, 0.f, 0.f, 0.f);
        #pragma unroll 4
        for (int w = 0; w < WIN; w++) {
            float a = scrow[w];
            float4 p = pb[(size_t)w * 22];
            acc.x += a * p.x; acc.y += a * p.y; acc.z += a * p.z; acc.w += a * p.w;
        }
        float4 ad;
        if (PER_TOKEN_ADD) ad = ((const float4*)(addv + (size_t)tok * OUTF))[lane];
        else               ad = ((const float4*)addv)[lane];
        float4 r;
        r.x = sigmoid_fast(acc.x + ad.x);
        r.y = sigmoid_fast(acc.y + ad.y);
        r.z = sigmoid_fast(acc.z + ad.z);
        r.w = sigmoid_fast(acc.w + ad.w);
        ((float4*)(p_out + (size_t)tok * OUTF))[lane] = r;
    }
}

// ---------------------------------------------------------------------------
// k2b: 8 tokens/block, 2-way K-split, 448 threads (432 active).
// ---------------------------------------------------------------------------
#define K2_TT 8
__global__ void __launch_bounds__(448) k2b_gc_xl(
    const float* __restrict__ Wac, const float* __restrict__ bac,
    const float* __restrict__ Wlc, const float* __restrict__ blc,
    const float* __restrict__ out)
{
    __shared__ __align__(16) float A[176][K2_TT];
    __shared__ float part[216][K2_TT];
    const int tok0 = blockIdx.x * K2_TT;
    const int tid = threadIdx.x;

    for (int idx = tid; idx < 176 * K2_TT; idx += 448) {
        int tt = idx / 176, r = idx - tt * 176;
        float v = (r < 88)
            ? out[FEAT_OFF  + (size_t)(tok0 + tt) * OUTF + r]
            : out[ONSET_OFF + (size_t)(tok0 + tt) * OUTF + (r - 88)];
        A[r][tt] = v;
    }
    __syncthreads();

    const int s = (tid >= 216);
    const int j = tid - s * 216;
    const bool active = (tid < 432);

    float rv[K2_TT];
    if (active) {
        const float* wp;
        int stride;
        if (j < 128) { wp = Wac + j;         stride = MODEL; }
        else         { wp = Wlc + (j - 128); stride = OUTF;  }
        wp += (size_t)(s * 88) * stride;

        unsigned long long acc[K2_TT / 2];
        #pragma unroll
        for (int p = 0; p < K2_TT / 2; p++) acc[p] = 0ull;

        const int k0 = s * 88;
        #pragma unroll 4
        for (int k = k0; k < k0 + 88; k++) {
            float w = *wp; wp += stride;
            unsigned long long ww = pkf2(w, w);
            const unsigned long long* row = (const unsigned long long*)&A[k][0];
            #pragma unroll
            for (int p = 0; p < K2_TT / 2; p++) fma2(acc[p], row[p], ww);
        }
        #pragma unroll
        for (int p = 0; p < K2_TT / 2; p++) {
            float2 r = upk(acc[p]);
            rv[2*p] = r.x; rv[2*p+1] = r.y;
        }
        if (s == 1) {
            #pragma unroll
            for (int tt = 0; tt < K2_TT; tt++) part[j][tt] = rv[tt];
        }
    }
    __syncthreads();

    if (active && s == 0) {
        if (j < 128) {
            float bias = bac[j];
            #pragma unroll
            for (int tt = 0; tt < K2_TT; tt++)
                g_gc[(size_t)(tok0 + tt) * MODEL + j] = rv[tt] + part[j][tt] + bias;
        } else {
            int m = j - 128;
            float bias = blc[m];
            #pragma unroll
            for (int tt = 0; tt < K2_TT; tt++)
                g_xl[(size_t)(tok0 + tt) * OUTF + m] = rv[tt] + part[j][tt] + bias;
        }
    }
}

extern "C" void kernel_launch(void* const* d_in, const int* in_sizes, int n_in,
                              void* d_out, int out_size)
{
    const float* spec = (const float*)d_in[0];
    const float* Wf   = (const float*)d_in[1];
    const float* bf   = (const float*)d_in[2];
    const float* Wao  = (const float*)d_in[3];
    const float* bao  = (const float*)d_in[4];
    const float* vo   = (const float*)d_in[5];
    const float* Wl1  = (const float*)d_in[6];
    const float* bl1  = (const float*)d_in[7];
    const float* Wac  = (const float*)d_in[8];
    const float* bac  = (const float*)d_in[9];
    const float* vc   = (const float*)d_in[10];
    const float* Wlc  = (const float*)d_in[11];
    const float* blc  = (const float*)d_in[12];
    float* out = (float*)d_out;

    float *p_go, *p_uo, *p_uc, *p_gc, *p_p12, *p_xl;
    cudaGetSymbolAddress((void**)&p_go,  g_go);
    cudaGetSymbolAddress((void**)&p_uo,  g_uo);
    cudaGetSymbolAddress((void**)&p_uc,  g_uc);
    cudaGetSymbolAddress((void**)&p_gc,  g_gc);
    cudaGetSymbolAddress((void**)&p_p12, g_p12);
    cudaGetSymbolAddress((void**)&p_xl,  g_xl);

    const int smem_bytes =
        (AT_ROWS * UPITCH + AT_ROWS * OUTF + AT_TT * MODEL + MODEL + AT_TT * 64) * 4;
    cudaFuncSetAttribute(k_attn_tiled<false>,
                         cudaFuncAttributeMaxDynamicSharedMemorySize, smem_bytes);
    cudaFuncSetAttribute(k_attn_tiled<true>,
                         cudaFuncAttributeMaxDynamicSharedMemorySize, smem_bytes);

    k1_proj<<<NTOK / K1_TT, 384>>>(spec, Wf, bf, Wao, bao, Wac, Wl1, Wlc, out);
    k_attn_tiled<false><<<NTOK / AT_TT, 512, smem_bytes>>>(
        p_go, p_uo, vo, bl1, p_p12, 0, out + AONSET_OFF, out + ONSET_OFF);
    k2b_gc_xl<<<NTOK / K2_TT, 448>>>(Wac, bac, Wlc, blc, out);
    k_attn_tiled<true><<<NTOK / AT_TT, 512, smem_bytes>>>(
        p_gc, p_uc, vc, p_xl, p_p12, 88, out + AFRAME_OFF, out + FRAME_OFF);
}